// round 1
// baseline (speedup 1.0000x reference)
#include <cuda_runtime.h>
#include <math.h>

// ---------------------------------------------------------------------------
// ChunkedCrossAttention  (B=4, S=1024, D=1024, H=16, Dk=64, CL=64, N=2, NL=128)
// Pipeline: out<-h (memcpy) ; rmsnorm(shifted h)->hn ; Q=hn@Wq ; K=e@Wk ; V=e@Wv
//           attention per (b,c,h) ; O=AO@Wo fused with +63-row shift-add into out
// All GEMMs: TF32 mma.sync.m16n8k8, fp32 accumulate.
// ---------------------------------------------------------------------------

__device__ float g_hn[4u * 1024 * 1024];   // [4096,1024]
__device__ float g_q [4u * 1024 * 1024];   // [4096,1024]
__device__ float g_k [16u * 1024 * 1024];  // [16384,1024]
__device__ float g_v [16u * 1024 * 1024];  // [16384,1024]
__device__ float g_ao[4u * 1024 * 1024];   // [4096,1024]

__device__ __forceinline__ float tf32_round(float x) {
    unsigned u;
    asm("cvt.rna.tf32.f32 %0, %1;\n" : "=r"(u) : "f"(x));
    return __uint_as_float(u);
}

__device__ __forceinline__ float4 tf4(float4 v) {
    float4 r;
    r.x = tf32_round(v.x); r.y = tf32_round(v.y);
    r.z = tf32_round(v.z); r.w = tf32_round(v.w);
    return r;
}

__device__ __forceinline__ void mma_tf32(float* c, const unsigned* a, const unsigned* b) {
    asm volatile(
        "mma.sync.aligned.m16n8k8.row.col.f32.tf32.tf32.f32 "
        "{%0,%1,%2,%3}, {%4,%5,%6,%7}, {%8,%9}, {%0,%1,%2,%3};\n"
        : "+f"(c[0]), "+f"(c[1]), "+f"(c[2]), "+f"(c[3])
        : "r"(a[0]), "r"(a[1]), "r"(a[2]), "r"(a[3]), "r"(b[0]), "r"(b[1]));
}

// ---------------------------------------------------------------------------
// RMSNorm of h[b, p+63, :] -> hn[b*1024+p, :]; rows p>=961 zeroed.
// ---------------------------------------------------------------------------
__global__ __launch_bounds__(256)
void rmsnorm_kernel(const float* __restrict__ h, const float* __restrict__ g,
                    float* __restrict__ hn)
{
    const int row = blockIdx.x;           // 0..4095
    const int b = row >> 10, p = row & 1023;
    const int t = threadIdx.x;            // one float4 per thread
    float4* dst = reinterpret_cast<float4*>(hn + (size_t)row * 1024);
    if (p >= 961) { dst[t] = make_float4(0.f, 0.f, 0.f, 0.f); return; }

    const float4* src = reinterpret_cast<const float4*>(h + ((size_t)(b * 1024 + p + 63)) * 1024);
    float4 x = src[t];
    float s = x.x * x.x + x.y * x.y + x.z * x.z + x.w * x.w;
    #pragma unroll
    for (int o = 16; o; o >>= 1) s += __shfl_xor_sync(0xffffffffu, s, o);
    __shared__ float red[8];
    if ((t & 31) == 0) red[t >> 5] = s;
    __syncthreads();
    float total = red[0] + red[1] + red[2] + red[3] + red[4] + red[5] + red[6] + red[7];
    float inv = rsqrtf(total * (1.f / 1024.f) + 1e-8f);
    float4 gg = reinterpret_cast<const float4*>(g)[t];
    dst[t] = make_float4(x.x * gg.x * inv, x.y * gg.y * inv, x.z * gg.z * inv, x.w * gg.w * inv);
}

// ---------------------------------------------------------------------------
// TF32 GEMM: C[M,1024] = A[M,1024] @ B[1024,1024] + bias
// mode 0: plain store. mode 1: p=row%1024; if p<961: C[(row+63)*1024+col] += val
// Block 128x128, BK=16, 256 threads = 8 warps (4m x 2n), warp tile 32x64.
// ---------------------------------------------------------------------------
__global__ __launch_bounds__(256, 2)
void gemm_tf32(const float* __restrict__ A, const float* __restrict__ Bm,
               const float* __restrict__ bias, float* __restrict__ C, int mode)
{
    __shared__ float As[2][128][20];   // pad 16->20: conflict-free A-frag LDS
    __shared__ float Bs[2][16][136];   // pad 128->136: conflict-free B-frag LDS

    const int tid  = threadIdx.x;
    const int lane = tid & 31;
    const int warp = tid >> 5;
    const int wm = (warp >> 1) * 32;
    const int wn = (warp & 1) * 64;
    const int bm = blockIdx.y * 128;
    const int bn = blockIdx.x * 128;

    const int ar  = tid >> 2;            // 0..63 (rows ar, ar+64)
    const int ak  = (tid & 3) * 4;       // k within tile
    const int bkr = tid >> 5;            // 0..7 (rows bkr, bkr+8)
    const int bnc = (tid & 31) * 4;      // n within tile

    const float* Ag0 = A + (size_t)(bm + ar) * 1024 + ak;
    const float* Ag1 = A + (size_t)(bm + ar + 64) * 1024 + ak;
    const float* Bg0 = Bm + (size_t)bkr * 1024 + bn + bnc;
    const float* Bg1 = Bm + (size_t)(bkr + 8) * 1024 + bn + bnc;

    float acc[2][8][4];
    #pragma unroll
    for (int i = 0; i < 2; i++)
        #pragma unroll
        for (int j = 0; j < 8; j++)
            #pragma unroll
            for (int q = 0; q < 4; q++) acc[i][j][q] = 0.f;

    float4 ra0, ra1, rb0, rb1;
    ra0 = *reinterpret_cast<const float4*>(Ag0);
    ra1 = *reinterpret_cast<const float4*>(Ag1);
    rb0 = *reinterpret_cast<const float4*>(Bg0);
    rb1 = *reinterpret_cast<const float4*>(Bg1);
    *reinterpret_cast<float4*>(&As[0][ar][ak])      = tf4(ra0);
    *reinterpret_cast<float4*>(&As[0][ar + 64][ak]) = tf4(ra1);
    *reinterpret_cast<float4*>(&Bs[0][bkr][bnc])    = tf4(rb0);
    *reinterpret_cast<float4*>(&Bs[0][bkr + 8][bnc])= tf4(rb1);
    __syncthreads();

    const int NKT = 1024 / 16;  // 64
    for (int kt = 0; kt < NKT; ++kt) {
        const int buf = kt & 1;
        if (kt + 1 < NKT) {
            ra0 = *reinterpret_cast<const float4*>(Ag0 + (size_t)(kt + 1) * 16);
            ra1 = *reinterpret_cast<const float4*>(Ag1 + (size_t)(kt + 1) * 16);
            rb0 = *reinterpret_cast<const float4*>(Bg0 + (size_t)(kt + 1) * 16 * 1024);
            rb1 = *reinterpret_cast<const float4*>(Bg1 + (size_t)(kt + 1) * 16 * 1024);
        }
        #pragma unroll
        for (int ks = 0; ks < 2; ++ks) {
            unsigned af[2][4];
            #pragma unroll
            for (int mt = 0; mt < 2; ++mt) {
                const int r0 = wm + mt * 16 + (lane >> 2);
                const int c0 = ks * 8 + (lane & 3);
                af[mt][0] = __float_as_uint(As[buf][r0][c0]);
                af[mt][1] = __float_as_uint(As[buf][r0 + 8][c0]);
                af[mt][2] = __float_as_uint(As[buf][r0][c0 + 4]);
                af[mt][3] = __float_as_uint(As[buf][r0 + 8][c0 + 4]);
            }
            #pragma unroll
            for (int nt = 0; nt < 8; ++nt) {
                const int n0 = wn + nt * 8 + (lane >> 2);
                const int k0 = ks * 8 + (lane & 3);
                unsigned bf[2];
                bf[0] = __float_as_uint(Bs[buf][k0][n0]);
                bf[1] = __float_as_uint(Bs[buf][k0 + 4][n0]);
                mma_tf32(acc[0][nt], af[0], bf);
                mma_tf32(acc[1][nt], af[1], bf);
            }
        }
        if (kt + 1 < NKT) {
            *reinterpret_cast<float4*>(&As[buf ^ 1][ar][ak])       = tf4(ra0);
            *reinterpret_cast<float4*>(&As[buf ^ 1][ar + 64][ak])  = tf4(ra1);
            *reinterpret_cast<float4*>(&Bs[buf ^ 1][bkr][bnc])     = tf4(rb0);
            *reinterpret_cast<float4*>(&Bs[buf ^ 1][bkr + 8][bnc]) = tf4(rb1);
            __syncthreads();
        }
    }

    #pragma unroll
    for (int mt = 0; mt < 2; ++mt) {
        #pragma unroll
        for (int nt = 0; nt < 8; ++nt) {
            const int row = bm + wm + mt * 16 + (lane >> 2);
            const int col = bn + wn + nt * 8 + (lane & 3) * 2;
            const float bv0 = bias[col], bv1 = bias[col + 1];
            const float v00 = acc[mt][nt][0] + bv0;
            const float v01 = acc[mt][nt][1] + bv1;
            const float v10 = acc[mt][nt][2] + bv0;
            const float v11 = acc[mt][nt][3] + bv1;
            if (mode == 0) {
                C[(size_t)row * 1024 + col]           = v00;
                C[(size_t)row * 1024 + col + 1]       = v01;
                C[(size_t)(row + 8) * 1024 + col]     = v10;
                C[(size_t)(row + 8) * 1024 + col + 1] = v11;
            } else {
                const int p = row & 1023;
                if (p < 961) {
                    const size_t o = (size_t)(row + 63) * 1024 + col;
                    C[o]     += v00;
                    C[o + 1] += v01;
                }
                const int p2 = (row + 8) & 1023;
                if (p2 < 961) {
                    const size_t o = (size_t)(row + 71) * 1024 + col;
                    C[o]     += v10;
                    C[o + 1] += v11;
                }
            }
        }
    }
}

// ---------------------------------------------------------------------------
// Attention: one block per (b, chunk, head). 128 threads = 4 warps (2m x 2n).
// logits[64,256] = q[64,64] @ k[256,64]^T * 0.125 ; softmax ; o = attn @ v[256,64]
// ---------------------------------------------------------------------------
#define ATTN_SMEM_FLOATS (64 * 68 + 128 * 68 + 64 * 257)
#define ATTN_SMEM_BYTES  (ATTN_SMEM_FLOATS * 4)

__global__ __launch_bounds__(128)
void attn_kernel(const float* __restrict__ Q, const float* __restrict__ Kt,
                 const float* __restrict__ Vt, float* __restrict__ AO)
{
    extern __shared__ float sm[];
    float (*q_s)[68]   = reinterpret_cast<float(*)[68]>(sm);
    float (*kv_s)[68]  = reinterpret_cast<float(*)[68]>(sm + 64 * 68);
    float (*l_s)[257]  = reinterpret_cast<float(*)[257]>(sm + 64 * 68 + 128 * 68);

    const int bid = blockIdx.x;
    const int b  = bid >> 8;
    const int c  = (bid >> 4) & 15;
    const int hh = bid & 15;
    const int tid  = threadIdx.x;
    const int lane = tid & 31;
    const int warp = tid >> 5;

    const size_t qbase  = ((size_t)(b * 1024 + c * 64)) * 1024 + hh * 64;
    const size_t kvbase = ((size_t)((b * 16 + c) * 256)) * 1024 + hh * 64;

    // load q (tf32-rounded)
    for (int i = tid; i < 64 * 16; i += 128) {
        const int r = i >> 4, d4 = (i & 15) * 4;
        float4 v = *reinterpret_cast<const float4*>(Q + qbase + (size_t)r * 1024 + d4);
        *reinterpret_cast<float4*>(&q_s[r][d4]) = tf4(v);
    }

    const int wm = (warp >> 1) * 32;

    // ---- Pass 1: logits ----
    for (int it = 0; it < 2; ++it) {
        for (int i = tid; i < 128 * 16; i += 128) {
            const int r = i >> 4, d4 = (i & 15) * 4;
            float4 v = *reinterpret_cast<const float4*>(Kt + kvbase + (size_t)(it * 128 + r) * 1024 + d4);
            *reinterpret_cast<float4*>(&kv_s[r][d4]) = tf4(v);
        }
        __syncthreads();

        const int wn = (warp & 1) * 64;
        float acc[2][8][4];
        #pragma unroll
        for (int i = 0; i < 2; i++)
            #pragma unroll
            for (int j = 0; j < 8; j++)
                #pragma unroll
                for (int q = 0; q < 4; q++) acc[i][j][q] = 0.f;

        #pragma unroll
        for (int ks = 0; ks < 8; ++ks) {
            unsigned af[2][4];
            #pragma unroll
            for (int mt = 0; mt < 2; ++mt) {
                const int r0 = wm + mt * 16 + (lane >> 2);
                const int c0 = ks * 8 + (lane & 3);
                af[mt][0] = __float_as_uint(q_s[r0][c0]);
                af[mt][1] = __float_as_uint(q_s[r0 + 8][c0]);
                af[mt][2] = __float_as_uint(q_s[r0][c0 + 4]);
                af[mt][3] = __float_as_uint(q_s[r0 + 8][c0 + 4]);
            }
            #pragma unroll
            for (int nt = 0; nt < 8; ++nt) {
                const int n0 = wn + nt * 8 + (lane >> 2);
                const int k0 = ks * 8 + (lane & 3);
                unsigned bf[2];
                bf[0] = __float_as_uint(kv_s[n0][k0]);      // B[k][n] = k_tok[n][k]
                bf[1] = __float_as_uint(kv_s[n0][k0 + 4]);
                mma_tf32(acc[0][nt], af[0], bf);
                mma_tf32(acc[1][nt], af[1], bf);
            }
        }
        #pragma unroll
        for (int mt = 0; mt < 2; ++mt)
            #pragma unroll
            for (int nt = 0; nt < 8; ++nt) {
                const int r  = wm + mt * 16 + (lane >> 2);
                const int cl = it * 128 + wn + nt * 8 + (lane & 3) * 2;
                l_s[r][cl]         = acc[mt][nt][0] * 0.125f;
                l_s[r][cl + 1]     = acc[mt][nt][1] * 0.125f;
                l_s[r + 8][cl]     = acc[mt][nt][2] * 0.125f;
                l_s[r + 8][cl + 1] = acc[mt][nt][3] * 0.125f;
            }
        __syncthreads();
    }

    // ---- softmax over 256 (rows 0..63, one thread each) ----
    if (tid < 64) {
        float* row = l_s[tid];
        float mx = row[0];
        for (int j = 1; j < 256; ++j) mx = fmaxf(mx, row[j]);
        float s = 0.f;
        for (int j = 0; j < 256; ++j) { float ee = __expf(row[j] - mx); row[j] = ee; s += ee; }
        const float inv = 1.f / s;
        for (int j = 0; j < 256; ++j) row[j] = tf32_round(row[j] * inv);
    }
    __syncthreads();

    // ---- Pass 2: o = attn @ v ----
    const int wn2 = (warp & 1) * 32;
    float acc2[2][4][4];
    #pragma unroll
    for (int i = 0; i < 2; i++)
        #pragma unroll
        for (int j = 0; j < 4; j++)
            #pragma unroll
            for (int q = 0; q < 4; q++) acc2[i][j][q] = 0.f;

    for (int it = 0; it < 2; ++it) {
        if (it) __syncthreads();
        for (int i = tid; i < 128 * 16; i += 128) {
            const int r = i >> 4, d4 = (i & 15) * 4;
            float4 v = *reinterpret_cast<const float4*>(Vt + kvbase + (size_t)(it * 128 + r) * 1024 + d4);
            *reinterpret_cast<float4*>(&kv_s[r][d4]) = tf4(v);
        }
        __syncthreads();

        #pragma unroll
        for (int ks = 0; ks < 16; ++ks) {
            unsigned af[2][4];
            #pragma unroll
            for (int mt = 0; mt < 2; ++mt) {
                const int r0 = wm + mt * 16 + (lane >> 2);
                const int c0 = it * 128 + ks * 8 + (lane & 3);
                af[mt][0] = __float_as_uint(l_s[r0][c0]);
                af[mt][1] = __float_as_uint(l_s[r0 + 8][c0]);
                af[mt][2] = __float_as_uint(l_s[r0][c0 + 4]);
                af[mt][3] = __float_as_uint(l_s[r0 + 8][c0 + 4]);
            }
            #pragma unroll
            for (int nt = 0; nt < 4; ++nt) {
                const int n0 = wn2 + nt * 8 + (lane >> 2);
                const int k0 = ks * 8 + (lane & 3);
                unsigned bf[2];
                bf[0] = __float_as_uint(kv_s[k0][n0]);      // B[k][n] = v[k][n]
                bf[1] = __float_as_uint(kv_s[k0 + 4][n0]);
                mma_tf32(acc2[0][nt], af[0], bf);
                mma_tf32(acc2[1][nt], af[1], bf);
            }
        }
    }

    #pragma unroll
    for (int mt = 0; mt < 2; ++mt)
        #pragma unroll
        for (int nt = 0; nt < 4; ++nt) {
            const int r  = wm + mt * 16 + (lane >> 2);
            const int cl = wn2 + nt * 8 + (lane & 3) * 2;
            const size_t o = qbase + (size_t)r * 1024 + cl;
            AO[o]               = acc2[mt][nt][0];
            AO[o + 1]           = acc2[mt][nt][1];
            AO[o + 8 * 1024]     = acc2[mt][nt][2];
            AO[o + 8 * 1024 + 1] = acc2[mt][nt][3];
        }
}

// ---------------------------------------------------------------------------
extern "C" void kernel_launch(void* const* d_in, const int* in_sizes, int n_in,
                              void* d_out, int out_size)
{
    const float* h  = (const float*)d_in[0];
    const float* e  = (const float*)d_in[1];
    const float* g  = (const float*)d_in[2];
    const float* Wq = (const float*)d_in[3];
    const float* bq = (const float*)d_in[4];
    const float* Wk = (const float*)d_in[5];
    const float* bk = (const float*)d_in[6];
    const float* Wv = (const float*)d_in[7];
    const float* bv = (const float*)d_in[8];
    const float* Wo = (const float*)d_in[9];
    const float* bo = (const float*)d_in[10];
    float* out = (float*)d_out;

    cudaFuncSetAttribute(attn_kernel, cudaFuncAttributeMaxDynamicSharedMemorySize, ATTN_SMEM_BYTES);

    void *p_hn, *p_q, *p_k, *p_v, *p_ao;
    cudaGetSymbolAddress(&p_hn, g_hn);
    cudaGetSymbolAddress(&p_q,  g_q);
    cudaGetSymbolAddress(&p_k,  g_k);
    cudaGetSymbolAddress(&p_v,  g_v);
    cudaGetSymbolAddress(&p_ao, g_ao);

    // out = h (residual; also rows 0..62 of each batch)
    cudaMemcpyAsync(out, h, (size_t)4 * 1024 * 1024 * sizeof(float),
                    cudaMemcpyDeviceToDevice, 0);

    rmsnorm_kernel<<<4096, 256>>>(h, g, (float*)p_hn);

    gemm_tf32<<<dim3(8, 32),  256>>>((const float*)p_hn, Wq, bq, (float*)p_q, 0);
    gemm_tf32<<<dim3(8, 128), 256>>>(e,                 Wk, bk, (float*)p_k, 0);
    gemm_tf32<<<dim3(8, 128), 256>>>(e,                 Wv, bv, (float*)p_v, 0);

    attn_kernel<<<1024, 128, ATTN_SMEM_BYTES>>>((const float*)p_q, (const float*)p_k,
                                                (const float*)p_v, (float*)p_ao);

    gemm_tf32<<<dim3(8, 32), 256>>>((const float*)p_ao, Wo, bo, out, 1);
}

// round 2
// speedup vs baseline: 2.2270x; 2.2270x over previous
#include <cuda_runtime.h>
#include <cuda_bf16.h>
#include <math.h>

// ---------------------------------------------------------------------------
// ChunkedCrossAttention bf16 pipeline (B=4,S=1024,D=1024,H=16,Dk=64,CL=64,N=2,NL=128)
// out<-h ; cvt(e,W*)->bf16 ; rmsnorm->bf16 hn ; Q/K/V proj (bf16 mma+ldmatrix) ;
// attention per (b,c,h) bf16 ; O-proj fused shift-add into out (fp32).
// ---------------------------------------------------------------------------

typedef __nv_bfloat16  bf16;
typedef __nv_bfloat162 bf162;

__device__ bf16 g_ebf[16u*1024*1024];
__device__ bf16 g_wqb[1024*1024];
__device__ bf16 g_wkb[1024*1024];
__device__ bf16 g_wvb[1024*1024];
__device__ bf16 g_wob[1024*1024];
__device__ bf16 g_hnb[4u*1024*1024];
__device__ bf16 g_qb [4u*1024*1024];
__device__ bf16 g_kb [16u*1024*1024];
__device__ bf16 g_vb [16u*1024*1024];
__device__ bf16 g_aob[4u*1024*1024];

__device__ __forceinline__ unsigned smaddr(const void* p) {
    return (unsigned)__cvta_generic_to_shared(p);
}
__device__ __forceinline__ void ldsm_x4(unsigned* r, unsigned addr) {
    asm volatile("ldmatrix.sync.aligned.m8n8.x4.shared.b16 {%0,%1,%2,%3}, [%4];"
        : "=r"(r[0]), "=r"(r[1]), "=r"(r[2]), "=r"(r[3]) : "r"(addr));
}
__device__ __forceinline__ void ldsm_x4_t(unsigned* r, unsigned addr) {
    asm volatile("ldmatrix.sync.aligned.m8n8.x4.trans.shared.b16 {%0,%1,%2,%3}, [%4];"
        : "=r"(r[0]), "=r"(r[1]), "=r"(r[2]), "=r"(r[3]) : "r"(addr));
}
__device__ __forceinline__ void mma_bf16(float* c, const unsigned* a, const unsigned* b) {
    asm volatile(
        "mma.sync.aligned.m16n8k16.row.col.f32.bf16.bf16.f32 "
        "{%0,%1,%2,%3}, {%4,%5,%6,%7}, {%8,%9}, {%0,%1,%2,%3};\n"
        : "+f"(c[0]), "+f"(c[1]), "+f"(c[2]), "+f"(c[3])
        : "r"(a[0]), "r"(a[1]), "r"(a[2]), "r"(a[3]), "r"(b[0]), "r"(b[1]));
}

// ---------------------------------------------------------------------------
__global__ __launch_bounds__(256)
void f2bf(const float4* __restrict__ src, bf162* __restrict__ dst, int n4)
{
    int i = blockIdx.x * blockDim.x + threadIdx.x;
    if (i < n4) {
        float4 v = src[i];
        dst[2*i]     = __floats2bfloat162_rn(v.x, v.y);
        dst[2*i + 1] = __floats2bfloat162_rn(v.z, v.w);
    }
}

// ---------------------------------------------------------------------------
// RMSNorm of h[b, p+63, :] -> hn_bf16[b*1024+p, :]; rows p>=961 zeroed.
// ---------------------------------------------------------------------------
__global__ __launch_bounds__(256)
void rmsnorm_bf16(const float* __restrict__ h, const float* __restrict__ g,
                  bf16* __restrict__ hn)
{
    const int row = blockIdx.x;           // 0..4095
    const int b = row >> 10, p = row & 1023;
    const int t = threadIdx.x;            // 4 elements per thread
    bf162* dst = reinterpret_cast<bf162*>(hn + (size_t)row * 1024);
    if (p >= 961) {
        bf162 z = __floats2bfloat162_rn(0.f, 0.f);
        dst[2*t] = z; dst[2*t + 1] = z;
        return;
    }
    const float4* src = reinterpret_cast<const float4*>(h + ((size_t)(b*1024 + p + 63)) * 1024);
    float4 x = src[t];
    float s = x.x*x.x + x.y*x.y + x.z*x.z + x.w*x.w;
    #pragma unroll
    for (int o = 16; o; o >>= 1) s += __shfl_xor_sync(0xffffffffu, s, o);
    __shared__ float red[8];
    if ((t & 31) == 0) red[t >> 5] = s;
    __syncthreads();
    float total = red[0]+red[1]+red[2]+red[3]+red[4]+red[5]+red[6]+red[7];
    float inv = rsqrtf(total * (1.f/1024.f) + 1e-8f);
    float4 gg = reinterpret_cast<const float4*>(g)[t];
    dst[2*t]     = __floats2bfloat162_rn(x.x*gg.x*inv, x.y*gg.y*inv);
    dst[2*t + 1] = __floats2bfloat162_rn(x.z*gg.z*inv, x.w*gg.w*inv);
}

// ---------------------------------------------------------------------------
// bf16 GEMM: C[M,1024] = A[M,1024] @ B[1024,1024] + bias.
// mode 0: store bf16 into Cb. mode 1: fp32 shift-add (+63 rows) into Cf.
// Block 128x128, BK=32, 256 threads = 8 warps (4m x 2n), warp tile 32x64.
// m16n8k16 mma, ldmatrix fragment loads (conflict-free padded strides).
// ---------------------------------------------------------------------------
__global__ __launch_bounds__(256, 2)
void gemm_bf16(const bf16* __restrict__ A, const bf16* __restrict__ Bm,
               const float* __restrict__ bias,
               bf16* __restrict__ Cb, float* __restrict__ Cf, int mode)
{
    __shared__ bf16 As[2][128][40];   // stride 80B: ldmatrix rows 20r%32 disjoint
    __shared__ bf16 Bs[2][32][136];   // stride 272B: 4r%32 disjoint

    const int tid  = threadIdx.x;
    const int lane = tid & 31;
    const int warp = tid >> 5;
    const int wm = (warp >> 1) * 32;
    const int wn = (warp & 1) * 64;
    const int bm = blockIdx.y * 128;
    const int bn = blockIdx.x * 128;

    // global->smem: A 128x32 (512 x16B chunks), B 32x128 (512 chunks); 2 each
    const bf16* Ag0 = A + (size_t)(bm + (tid >> 2)) * 1024 + (tid & 3) * 8;
    const bf16* Ag1 = Ag0 + (size_t)64 * 1024;
    const bf16* Bg0 = Bm + (size_t)(tid >> 4) * 1024 + bn + (tid & 15) * 8;
    const bf16* Bg1 = Bg0 + (size_t)16 * 1024;
    bf16* Asp0 = &As[0][tid >> 2][(tid & 3) * 8];
    bf16* Asp1 = &As[0][64 + (tid >> 2)][(tid & 3) * 8];
    bf16* Bsp0 = &Bs[0][tid >> 4][(tid & 15) * 8];
    bf16* Bsp1 = &Bs[0][16 + (tid >> 4)][(tid & 15) * 8];

    const unsigned a_base = smaddr(&As[0][wm + (lane & 15)][(lane >> 4) * 8]);
    const unsigned b_base = smaddr(&Bs[0][lane & 15][wn + (lane >> 4) * 8]);

    float acc[2][8][4];
    #pragma unroll
    for (int i = 0; i < 2; i++)
        #pragma unroll
        for (int j = 0; j < 8; j++)
            #pragma unroll
            for (int q = 0; q < 4; q++) acc[i][j][q] = 0.f;

    uint4 ra0 = *(const uint4*)Ag0, ra1 = *(const uint4*)Ag1;
    uint4 rb0 = *(const uint4*)Bg0, rb1 = *(const uint4*)Bg1;
    *(uint4*)Asp0 = ra0; *(uint4*)Asp1 = ra1;
    *(uint4*)Bsp0 = rb0; *(uint4*)Bsp1 = rb1;
    __syncthreads();

    const int NKT = 32;  // 1024/32
    for (int kt = 0; kt < NKT; ++kt) {
        const int buf = kt & 1;
        if (kt + 1 < NKT) {
            ra0 = *(const uint4*)(Ag0 + (size_t)(kt + 1) * 32);
            ra1 = *(const uint4*)(Ag1 + (size_t)(kt + 1) * 32);
            rb0 = *(const uint4*)(Bg0 + (size_t)(kt + 1) * 32 * 1024);
            rb1 = *(const uint4*)(Bg1 + (size_t)(kt + 1) * 32 * 1024);
        }
        #pragma unroll
        for (int ks = 0; ks < 2; ++ks) {
            unsigned af[2][4];
            ldsm_x4(af[0], a_base + buf*10240 + ks*32);
            ldsm_x4(af[1], a_base + buf*10240 + ks*32 + 1280);
            unsigned bq[4][4];
            #pragma unroll
            for (int nt = 0; nt < 4; ++nt)
                ldsm_x4_t(bq[nt], b_base + buf*8704 + ks*4352 + nt*32);
            #pragma unroll
            for (int nt = 0; nt < 4; ++nt) {
                mma_bf16(acc[0][nt*2],     af[0], &bq[nt][0]);
                mma_bf16(acc[1][nt*2],     af[1], &bq[nt][0]);
                mma_bf16(acc[0][nt*2 + 1], af[0], &bq[nt][2]);
                mma_bf16(acc[1][nt*2 + 1], af[1], &bq[nt][2]);
            }
        }
        if (kt + 1 < NKT) {
            const int nb = (buf ^ 1) * 5120;      // As buffer stride (elems)
            const int nbB = (buf ^ 1) * 4352;     // Bs buffer stride (elems)
            *(uint4*)(Asp0 + nb)  = ra0;
            *(uint4*)(Asp1 + nb)  = ra1;
            *(uint4*)(Bsp0 + nbB) = rb0;
            *(uint4*)(Bsp1 + nbB) = rb1;
            __syncthreads();
        }
    }

    #pragma unroll
    for (int mt = 0; mt < 2; ++mt) {
        #pragma unroll
        for (int nt = 0; nt < 8; ++nt) {
            const int row = bm + wm + mt*16 + (lane >> 2);
            const int col = bn + wn + nt*8 + (lane & 3)*2;
            const float b0 = bias[col], b1 = bias[col + 1];
            const float v00 = acc[mt][nt][0] + b0;
            const float v01 = acc[mt][nt][1] + b1;
            const float v10 = acc[mt][nt][2] + b0;
            const float v11 = acc[mt][nt][3] + b1;
            if (mode == 0) {
                *(bf162*)(Cb + (size_t)row * 1024 + col)       = __floats2bfloat162_rn(v00, v01);
                *(bf162*)(Cb + (size_t)(row + 8) * 1024 + col) = __floats2bfloat162_rn(v10, v11);
            } else {
                const int p = row & 1023;
                if (p < 961) {
                    const size_t o = (size_t)(row + 63) * 1024 + col;
                    Cf[o]     += v00;
                    Cf[o + 1] += v01;
                }
                const int p2 = (row + 8) & 1023;
                if (p2 < 961) {
                    const size_t o = (size_t)(row + 71) * 1024 + col;
                    Cf[o]     += v10;
                    Cf[o + 1] += v11;
                }
            }
        }
    }
}

// ---------------------------------------------------------------------------
// Attention per (b, chunk, head): 256 threads = 8 warps.
// logits[64,256] = q @ k^T * 0.125 ; softmax (4 lanes/row) ; o = P @ v.
// All mma bf16 m16n8k16 via ldmatrix; K and V both resident in smem.
// ---------------------------------------------------------------------------
// smem (bytes): q 64x72 bf16 = 9216 | k 256x72 = 36864 | v 256x72 = 36864
//               l 64x260 f32 = 66560 | p 64x264 bf16 = 33792  -> total 183296
#define ATTN_SMEM_BYTES 183296

__global__ __launch_bounds__(256)
void attn_bf16(const bf16* __restrict__ Q, const bf16* __restrict__ K,
               const bf16* __restrict__ V, bf16* __restrict__ AO)
{
    extern __shared__ char smraw[];
    bf16  (*q_s)[72]  = reinterpret_cast<bf16(*)[72]>(smraw);
    bf16  (*k_s)[72]  = reinterpret_cast<bf16(*)[72]>(smraw + 9216);
    bf16  (*v_s)[72]  = reinterpret_cast<bf16(*)[72]>(smraw + 46080);
    float (*l_s)[260] = reinterpret_cast<float(*)[260]>(smraw + 82944);
    bf16  (*p_s)[264] = reinterpret_cast<bf16(*)[264]>(smraw + 149504);

    const int bid = blockIdx.x;
    const int b  = bid >> 8, c = (bid >> 4) & 15, hh = bid & 15;
    const int tid = threadIdx.x, lane = tid & 31, warp = tid >> 5;

    const size_t qbase  = ((size_t)(b * 1024 + c * 64)) * 1024 + hh * 64;
    const size_t kvbase = ((size_t)((b * 16 + c) * 256)) * 1024 + hh * 64;

    // ---- loads: q 512 chunks (2/thr), k & v 2048 chunks (8/thr each) ----
    #pragma unroll
    for (int i = 0; i < 2; ++i) {
        int ch = tid + i * 256;
        int r = ch >> 3, sg = ch & 7;
        *(uint4*)&q_s[r][sg * 8] = *(const uint4*)(Q + qbase + (size_t)r * 1024 + sg * 8);
    }
    #pragma unroll
    for (int i = 0; i < 8; ++i) {
        int ch = tid + i * 256;
        int r = ch >> 3, sg = ch & 7;
        *(uint4*)&k_s[r][sg * 8] = *(const uint4*)(K + kvbase + (size_t)r * 1024 + sg * 8);
        *(uint4*)&v_s[r][sg * 8] = *(const uint4*)(V + kvbase + (size_t)r * 1024 + sg * 8);
    }
    __syncthreads();

    const int wm = (warp >> 2) * 32;

    // ---- logits: warps 2m x 4n; warp tile 32 x 64 ----
    {
        const int wnl = (warp & 3) * 64;
        float acc[2][8][4];
        #pragma unroll
        for (int i = 0; i < 2; i++)
            #pragma unroll
            for (int j = 0; j < 8; j++)
                #pragma unroll
                for (int q = 0; q < 4; q++) acc[i][j][q] = 0.f;

        const unsigned a0 = smaddr(&q_s[wm + (lane & 15)][(lane >> 4) * 8]);
        // non-trans B from k_s: row = n0 + (lane&7) + ((lane>>4)&1)*8, col d0 + ((lane>>3)&1)*8
        const unsigned b0 = smaddr(&k_s[wnl + (lane & 7) + ((lane >> 4) & 1) * 8][((lane >> 3) & 1) * 8]);

        #pragma unroll
        for (int ks = 0; ks < 4; ++ks) {           // d = ks*16
            unsigned af[2][4];
            ldsm_x4(af[0], a0 + ks*32);
            ldsm_x4(af[1], a0 + ks*32 + 16*144);
            #pragma unroll
            for (int nt = 0; nt < 4; ++nt) {
                unsigned bq[4];
                ldsm_x4(bq, b0 + nt*16*144 + ks*32);
                mma_bf16(acc[0][nt*2],     af[0], bq);
                mma_bf16(acc[0][nt*2 + 1], af[0], bq + 2);
                mma_bf16(acc[1][nt*2],     af[1], bq);
                mma_bf16(acc[1][nt*2 + 1], af[1], bq + 2);
            }
        }
        #pragma unroll
        for (int mt = 0; mt < 2; ++mt)
            #pragma unroll
            for (int nt = 0; nt < 8; ++nt) {
                const int r  = wm + mt*16 + (lane >> 2);
                const int cl = wnl + nt*8 + (lane & 3)*2;
                l_s[r][cl]       = acc[mt][nt][0] * 0.125f;
                l_s[r][cl + 1]   = acc[mt][nt][1] * 0.125f;
                l_s[r + 8][cl]     = acc[mt][nt][2] * 0.125f;
                l_s[r + 8][cl + 1] = acc[mt][nt][3] * 0.125f;
            }
    }
    __syncthreads();

    // ---- softmax: 4 lanes per row, strided cols (bank-conflict-free) ----
    {
        const int row = tid >> 2, seg = tid & 3;
        float* lr = l_s[row];
        float mx = -1e30f;
        #pragma unroll
        for (int j = 0; j < 64; ++j) mx = fmaxf(mx, lr[seg + 4*j]);
        mx = fmaxf(mx, __shfl_xor_sync(0xffffffffu, mx, 1));
        mx = fmaxf(mx, __shfl_xor_sync(0xffffffffu, mx, 2));
        float s = 0.f;
        #pragma unroll
        for (int j = 0; j < 64; ++j) {
            float e = __expf(lr[seg + 4*j] - mx);
            lr[seg + 4*j] = e;
            s += e;
        }
        s += __shfl_xor_sync(0xffffffffu, s, 1);
        s += __shfl_xor_sync(0xffffffffu, s, 2);
        const float inv = 1.f / s;
        #pragma unroll
        for (int j = 0; j < 64; ++j)
            p_s[row][seg + 4*j] = __float2bfloat16(lr[seg + 4*j] * inv);
    }
    __syncthreads();

    // ---- PV: warps 2m x 4n; warp tile 32 x 16; k = 256 ----
    {
        const int wn2 = (warp & 3) * 16;
        float acc2[2][2][4];
        #pragma unroll
        for (int i = 0; i < 2; i++)
            #pragma unroll
            for (int j = 0; j < 2; j++)
                #pragma unroll
                for (int q = 0; q < 4; q++) acc2[i][j][q] = 0.f;

        const unsigned pa = smaddr(&p_s[wm + (lane & 15)][(lane >> 4) * 8]);
        const unsigned va = smaddr(&v_s[lane & 15][wn2 + (lane >> 4) * 8]);

        #pragma unroll
        for (int ks = 0; ks < 16; ++ks) {          // j = ks*16
            unsigned af[2][4];
            ldsm_x4(af[0], pa + ks*32);
            ldsm_x4(af[1], pa + ks*32 + 16*528);
            unsigned bq[4];
            ldsm_x4_t(bq, va + ks*16*144);
            mma_bf16(acc2[0][0], af[0], bq);
            mma_bf16(acc2[0][1], af[0], bq + 2);
            mma_bf16(acc2[1][0], af[1], bq);
            mma_bf16(acc2[1][1], af[1], bq + 2);
        }
        #pragma unroll
        for (int mt = 0; mt < 2; ++mt)
            #pragma unroll
            for (int nt = 0; nt < 2; ++nt) {
                const int r   = wm + mt*16 + (lane >> 2);
                const int col = wn2 + nt*8 + (lane & 3)*2;
                *(bf162*)(AO + qbase + (size_t)r * 1024 + col) =
                    __floats2bfloat162_rn(acc2[mt][nt][0], acc2[mt][nt][1]);
                *(bf162*)(AO + qbase + (size_t)(r + 8) * 1024 + col) =
                    __floats2bfloat162_rn(acc2[mt][nt][2], acc2[mt][nt][3]);
            }
    }
}

// ---------------------------------------------------------------------------
extern "C" void kernel_launch(void* const* d_in, const int* in_sizes, int n_in,
                              void* d_out, int out_size)
{
    const float* h  = (const float*)d_in[0];
    const float* e  = (const float*)d_in[1];
    const float* g  = (const float*)d_in[2];
    const float* Wq = (const float*)d_in[3];
    const float* bq = (const float*)d_in[4];
    const float* Wk = (const float*)d_in[5];
    const float* bk = (const float*)d_in[6];
    const float* Wv = (const float*)d_in[7];
    const float* bv = (const float*)d_in[8];
    const float* Wo = (const float*)d_in[9];
    const float* bo = (const float*)d_in[10];
    float* out = (float*)d_out;

    cudaFuncSetAttribute(attn_bf16, cudaFuncAttributeMaxDynamicSharedMemorySize, ATTN_SMEM_BYTES);

    void *p_ebf, *p_wq, *p_wk, *p_wv, *p_wo, *p_hn, *p_q, *p_k, *p_v, *p_ao;
    cudaGetSymbolAddress(&p_ebf, g_ebf);
    cudaGetSymbolAddress(&p_wq,  g_wqb);
    cudaGetSymbolAddress(&p_wk,  g_wkb);
    cudaGetSymbolAddress(&p_wv,  g_wvb);
    cudaGetSymbolAddress(&p_wo,  g_wob);
    cudaGetSymbolAddress(&p_hn,  g_hnb);
    cudaGetSymbolAddress(&p_q,   g_qb);
    cudaGetSymbolAddress(&p_k,   g_kb);
    cudaGetSymbolAddress(&p_v,   g_vb);
    cudaGetSymbolAddress(&p_ao,  g_aob);

    // residual: out = h (also covers rows 0..62 of each batch)
    cudaMemcpyAsync(out, h, (size_t)4 * 1024 * 1024 * sizeof(float),
                    cudaMemcpyDeviceToDevice, 0);

    // fp32 -> bf16 conversions
    f2bf<<<16384, 256>>>((const float4*)e,  (bf162*)p_ebf, 4194304);
    f2bf<<<1024,  256>>>((const float4*)Wq, (bf162*)p_wq,  262144);
    f2bf<<<1024,  256>>>((const float4*)Wk, (bf162*)p_wk,  262144);
    f2bf<<<1024,  256>>>((const float4*)Wv, (bf162*)p_wv,  262144);
    f2bf<<<1024,  256>>>((const float4*)Wo, (bf162*)p_wo,  262144);

    rmsnorm_bf16<<<4096, 256>>>(h, g, (bf16*)p_hn);

    gemm_bf16<<<dim3(8, 32),  256>>>((const bf16*)p_hn,  (const bf16*)p_wq, bq,
                                     (bf16*)p_q, nullptr, 0);
    gemm_bf16<<<dim3(8, 128), 256>>>((const bf16*)p_ebf, (const bf16*)p_wk, bk,
                                     (bf16*)p_k, nullptr, 0);
    gemm_bf16<<<dim3(8, 128), 256>>>((const bf16*)p_ebf, (const bf16*)p_wv, bv,
                                     (bf16*)p_v, nullptr, 0);

    attn_bf16<<<1024, 256, ATTN_SMEM_BYTES>>>((const bf16*)p_q, (const bf16*)p_k,
                                              (const bf16*)p_v, (bf16*)p_ao);

    gemm_bf16<<<dim3(8, 32), 256>>>((const bf16*)p_ao, (const bf16*)p_wo, bo,
                                    nullptr, out, 1);
}

// round 4
// speedup vs baseline: 2.2654x; 1.0173x over previous
#include <cuda_runtime.h>
#include <cuda_bf16.h>
#include <math.h>
#include <stdint.h>

// ---------------------------------------------------------------------------
// ChunkedCrossAttention (B=4,S=1024,D=1024,H=16,Dk=64,CL=64,N=2,NL=128)
// bf16 legacy-mma pipeline, cp.async 3-stage GEMM, fused K+V projection.
// ---------------------------------------------------------------------------

typedef __nv_bfloat16  bf16;
typedef __nv_bfloat162 bf162;

__device__ bf16 g_ebf[16u*1024*1024];
__device__ bf16 g_wqb[1024*1024];          // [k][n]
__device__ bf16 g_wkv[2u*1024*1024];       // [k][2048]: Wk | Wv
__device__ bf16 g_wob[1024*1024];
__device__ bf16 g_hnb[4u*1024*1024];
__device__ bf16 g_qb [4u*1024*1024];
__device__ bf16 g_kb [16u*1024*1024];
__device__ bf16 g_vb [16u*1024*1024];
__device__ bf16 g_aob[4u*1024*1024];

__device__ __forceinline__ unsigned smaddr(const void* p) {
    return (unsigned)__cvta_generic_to_shared(p);
}
__device__ __forceinline__ void cp16(uint32_t dst, const void* src) {
    asm volatile("cp.async.cg.shared.global [%0], [%1], 16;" :: "r"(dst), "l"(src));
}
#define CP_COMMIT() asm volatile("cp.async.commit_group;" ::: "memory")
#define CP_WAIT(n)  asm volatile("cp.async.wait_group %0;" :: "n"(n) : "memory")

__device__ __forceinline__ void ldsm_x4(unsigned* r, unsigned addr) {
    asm volatile("ldmatrix.sync.aligned.m8n8.x4.shared.b16 {%0,%1,%2,%3}, [%4];"
        : "=r"(r[0]), "=r"(r[1]), "=r"(r[2]), "=r"(r[3]) : "r"(addr));
}
__device__ __forceinline__ void ldsm_x4_t(unsigned* r, unsigned addr) {
    asm volatile("ldmatrix.sync.aligned.m8n8.x4.trans.shared.b16 {%0,%1,%2,%3}, [%4];"
        : "=r"(r[0]), "=r"(r[1]), "=r"(r[2]), "=r"(r[3]) : "r"(addr));
}
__device__ __forceinline__ void mma_bf16(float* c, const unsigned* a, const unsigned* b) {
    asm volatile(
        "mma.sync.aligned.m16n8k16.row.col.f32.bf16.bf16.f32 "
        "{%0,%1,%2,%3}, {%4,%5,%6,%7}, {%8,%9}, {%0,%1,%2,%3};\n"
        : "+f"(c[0]), "+f"(c[1]), "+f"(c[2]), "+f"(c[3])
        : "r"(a[0]), "r"(a[1]), "r"(a[2]), "r"(a[3]), "r"(b[0]), "r"(b[1]));
}

// ---------------------------------------------------------------------------
__global__ __launch_bounds__(256)
void f2bf(const float4* __restrict__ src, bf162* __restrict__ dst, int n4)
{
    int i = blockIdx.x * blockDim.x + threadIdx.x;
    if (i < n4) {
        float4 v = src[i];
        dst[2*i]     = __floats2bfloat162_rn(v.x, v.y);
        dst[2*i + 1] = __floats2bfloat162_rn(v.z, v.w);
    }
}

// concat conversion: Wk, Wv fp32 [1024][1024] -> bf16 [1024][2048]
__global__ __launch_bounds__(256)
void f2bf_cat(const float4* __restrict__ srcK, const float4* __restrict__ srcV,
              bf162* __restrict__ dst)
{
    int i = blockIdx.x * blockDim.x + threadIdx.x;   // 0..262143
    int k = i >> 8, j = i & 255;                      // 256 float4 per row
    float4 a = srcK[i], b = srcV[i];
    bf162* dk = dst + (size_t)k * 1024 + j * 2;
    dk[0] = __floats2bfloat162_rn(a.x, a.y);
    dk[1] = __floats2bfloat162_rn(a.z, a.w);
    bf162* dv = dk + 512;
    dv[0] = __floats2bfloat162_rn(b.x, b.y);
    dv[1] = __floats2bfloat162_rn(b.z, b.w);
}

// ---------------------------------------------------------------------------
__global__ __launch_bounds__(256)
void rmsnorm_bf16(const float* __restrict__ h, const float* __restrict__ g,
                  bf16* __restrict__ hn)
{
    const int row = blockIdx.x;
    const int b = row >> 10, p = row & 1023;
    const int t = threadIdx.x;
    bf162* dst = reinterpret_cast<bf162*>(hn + (size_t)row * 1024);
    if (p >= 961) {
        bf162 z = __floats2bfloat162_rn(0.f, 0.f);
        dst[2*t] = z; dst[2*t + 1] = z;
        return;
    }
    const float4* src = reinterpret_cast<const float4*>(h + ((size_t)(b*1024 + p + 63)) * 1024);
    float4 x = src[t];
    float s = x.x*x.x + x.y*x.y + x.z*x.z + x.w*x.w;
    #pragma unroll
    for (int o = 16; o; o >>= 1) s += __shfl_xor_sync(0xffffffffu, s, o);
    __shared__ float red[8];
    if ((t & 31) == 0) red[t >> 5] = s;
    __syncthreads();
    float total = red[0]+red[1]+red[2]+red[3]+red[4]+red[5]+red[6]+red[7];
    float inv = rsqrtf(total * (1.f/1024.f) + 1e-8f);
    float4 gg = reinterpret_cast<const float4*>(g)[t];
    dst[2*t]     = __floats2bfloat162_rn(x.x*gg.x*inv, x.y*gg.y*inv);
    dst[2*t + 1] = __floats2bfloat162_rn(x.z*gg.z*inv, x.w*gg.w*inv);
}

// ---------------------------------------------------------------------------
// cp.async 3-stage bf16 GEMM. Tile 128x256, BK=32, 256 thr = 8 warps (2m x 4n),
// warp tile 64x64. B is [k][Nb] row-major (trans-ldmatrix fragments).
// mode 0: bf16 store; cols < 1024 -> C1/bias1, >=1024 -> C2/bias2 (col-1024).
// mode 1: fp32 shift-add (+63 rows, p<961) into Cf with bias1.
// smem: A stages 3x10240 @0 ; B stages 3x16896 @30720 ; total 81408 B.
// ---------------------------------------------------------------------------
#define GEMM_SMEM 81408

__global__ __launch_bounds__(256, 1)
void gemm_cp(const bf16* __restrict__ A, const bf16* __restrict__ Bm,
             const float* __restrict__ bias1, const float* __restrict__ bias2,
             bf16* __restrict__ C1, bf16* __restrict__ C2,
             float* __restrict__ Cf, int Nb, int mode)
{
    extern __shared__ char dyn[];
    const uint32_t sbase = smaddr(dyn);

    const int tid = threadIdx.x, lane = tid & 31, warp = tid >> 5;
    const int bm = blockIdx.y * 128, bn = blockIdx.x * 256;
    const int wm = (warp >> 2) * 64, wn = (warp & 3) * 64;

    // copy descriptors: A 2 chunks/thread, B 4 chunks/thread (16B each)
    uint32_t a_off[2]; const bf16* a_src[2];
    #pragma unroll
    for (int i = 0; i < 2; ++i) {
        int c = tid + i * 256, r = c >> 2, g = c & 3;
        a_off[i] = r * 80 + g * 16;
        a_src[i] = A + (size_t)(bm + r) * 1024 + g * 8;
    }
    uint32_t b_off[4]; const bf16* b_src[4];
    #pragma unroll
    for (int i = 0; i < 4; ++i) {
        int c = tid + i * 256, r = c >> 5, g = c & 31;
        b_off[i] = 30720 + r * 528 + g * 16;
        b_src[i] = Bm + (size_t)r * Nb + bn + g * 8;
    }

    const uint32_t aa0 = sbase + (wm + (lane & 15)) * 80 + (lane >> 4) * 16;
    const uint32_t ba0 = sbase + 30720 + (lane & 15) * 528 + (wn + (lane >> 4) * 8) * 2;

    float acc[4][8][4];
    #pragma unroll
    for (int a = 0; a < 4; ++a)
        #pragma unroll
        for (int b = 0; b < 8; ++b)
            #pragma unroll
            for (int q = 0; q < 4; ++q) acc[a][b][q] = 0.f;

    // prologue: stages 0, 1
    #pragma unroll
    for (int s = 0; s < 2; ++s) {
        #pragma unroll
        for (int i = 0; i < 2; ++i) cp16(sbase + s*10240 + a_off[i], a_src[i] + s*32);
        #pragma unroll
        for (int i = 0; i < 4; ++i) cp16(sbase + s*16896 + b_off[i], b_src[i] + (size_t)s*32*Nb);
        CP_COMMIT();
    }
    CP_WAIT(1);
    __syncthreads();

    for (int kt = 0; kt < 32; ++kt) {
        const int stg = kt - (kt >= 3 ? 3 * ((kt * 0x5556) >> 16) : 0); // kt % 3
        const uint32_t aa = aa0 + stg * 10240;
        const uint32_t ba = ba0 + stg * 16896;
        #pragma unroll
        for (int ks = 0; ks < 2; ++ks) {
            unsigned af[4][4];
            #pragma unroll
            for (int mt = 0; mt < 4; ++mt) ldsm_x4(af[mt], aa + mt*1280 + ks*32);
            unsigned bq[4][4];
            #pragma unroll
            for (int nt = 0; nt < 4; ++nt) ldsm_x4_t(bq[nt], ba + ks*8448 + nt*32);
            #pragma unroll
            for (int mt = 0; mt < 4; ++mt)
                #pragma unroll
                for (int nt = 0; nt < 4; ++nt) {
                    mma_bf16(acc[mt][nt*2],     af[mt], bq[nt]);
                    mma_bf16(acc[mt][nt*2 + 1], af[mt], bq[nt] + 2);
                }
        }
        if (kt == 31) break;
        if (kt + 2 < 32) {
            const int ns = (kt + 2) - 3 * ((kt + 2) / 3);
            #pragma unroll
            for (int i = 0; i < 2; ++i)
                cp16(sbase + ns*10240 + a_off[i], a_src[i] + (kt + 2) * 32);
            #pragma unroll
            for (int i = 0; i < 4; ++i)
                cp16(sbase + ns*16896 + b_off[i], b_src[i] + (size_t)(kt + 2)*32*Nb);
            CP_COMMIT();
            CP_WAIT(1);
        } else {
            CP_WAIT(0);
        }
        __syncthreads();
    }

    // ---- epilogue ----
    #pragma unroll
    for (int mt = 0; mt < 4; ++mt) {
        #pragma unroll
        for (int j = 0; j < 8; ++j) {
            const int row  = bm + wm + mt * 16 + (lane >> 2);
            const int gcol = bn + wn + j * 8 + (lane & 3) * 2;
            if (mode == 0) {
                const float* bb = bias1; bf16* dst = C1; int cc = gcol;
                if (gcol >= 1024) { bb = bias2; dst = C2; cc = gcol - 1024; }
                const float b0 = bb[cc], b1 = bb[cc + 1];
                *(bf162*)(dst + (size_t)row * 1024 + cc) =
                    __floats2bfloat162_rn(acc[mt][j][0] + b0, acc[mt][j][1] + b1);
                *(bf162*)(dst + (size_t)(row + 8) * 1024 + cc) =
                    __floats2bfloat162_rn(acc[mt][j][2] + b0, acc[mt][j][3] + b1);
            } else {
                const float b0 = bias1[gcol], b1 = bias1[gcol + 1];
                const int p = row & 1023;
                if (p < 961) {
                    float* o = Cf + (size_t)(row + 63) * 1024 + gcol;
                    o[0] += acc[mt][j][0] + b0;
                    o[1] += acc[mt][j][1] + b1;
                }
                const int p2 = (row + 8) & 1023;
                if (p2 < 961) {
                    float* o = Cf + (size_t)(row + 71) * 1024 + gcol;
                    o[0] += acc[mt][j][2] + b0;
                    o[1] += acc[mt][j][3] + b1;
                }
            }
        }
    }
}

// ---------------------------------------------------------------------------
// Attention per (b, chunk, head): 256 threads; bf16 mma (round-2 verified).
// ---------------------------------------------------------------------------
#define ATTN_SMEM_BYTES 183296

__global__ __launch_bounds__(256)
void attn_bf16(const bf16* __restrict__ Q, const bf16* __restrict__ K,
               const bf16* __restrict__ V, bf16* __restrict__ AO)
{
    extern __shared__ char smraw[];
    bf16  (*q_s)[72]  = reinterpret_cast<bf16(*)[72]>(smraw);
    bf16  (*k_s)[72]  = reinterpret_cast<bf16(*)[72]>(smraw + 9216);
    bf16  (*v_s)[72]  = reinterpret_cast<bf16(*)[72]>(smraw + 46080);
    float (*l_s)[260] = reinterpret_cast<float(*)[260]>(smraw + 82944);
    bf16  (*p_s)[264] = reinterpret_cast<bf16(*)[264]>(smraw + 149504);

    const int bid = blockIdx.x;
    const int b  = bid >> 8, c = (bid >> 4) & 15, hh = bid & 15;
    const int tid = threadIdx.x, lane = tid & 31, warp = tid >> 5;

    const size_t qbase  = ((size_t)(b * 1024 + c * 64)) * 1024 + hh * 64;
    const size_t kvbase = ((size_t)((b * 16 + c) * 256)) * 1024 + hh * 64;

    #pragma unroll
    for (int i = 0; i < 2; ++i) {
        int ch = tid + i * 256;
        int r = ch >> 3, sg = ch & 7;
        *(uint4*)&q_s[r][sg * 8] = *(const uint4*)(Q + qbase + (size_t)r * 1024 + sg * 8);
    }
    #pragma unroll
    for (int i = 0; i < 8; ++i) {
        int ch = tid + i * 256;
        int r = ch >> 3, sg = ch & 7;
        *(uint4*)&k_s[r][sg * 8] = *(const uint4*)(K + kvbase + (size_t)r * 1024 + sg * 8);
        *(uint4*)&v_s[r][sg * 8] = *(const uint4*)(V + kvbase + (size_t)r * 1024 + sg * 8);
    }
    __syncthreads();

    const int wm = (warp >> 2) * 32;

    { // logits
        const int wnl = (warp & 3) * 64;
        float acc[2][8][4];
        #pragma unroll
        for (int i = 0; i < 2; i++)
            #pragma unroll
            for (int j = 0; j < 8; j++)
                #pragma unroll
                for (int q = 0; q < 4; q++) acc[i][j][q] = 0.f;

        const unsigned a0 = smaddr(&q_s[wm + (lane & 15)][(lane >> 4) * 8]);
        const unsigned b0 = smaddr(&k_s[wnl + (lane & 7) + ((lane >> 4) & 1) * 8][((lane >> 3) & 1) * 8]);

        #pragma unroll
        for (int ks = 0; ks < 4; ++ks) {
            unsigned af[2][4];
            ldsm_x4(af[0], a0 + ks*32);
            ldsm_x4(af[1], a0 + ks*32 + 16*144);
            #pragma unroll
            for (int nt = 0; nt < 4; ++nt) {
                unsigned bq[4];
                ldsm_x4(bq, b0 + nt*16*144 + ks*32);
                mma_bf16(acc[0][nt*2],     af[0], bq);
                mma_bf16(acc[0][nt*2 + 1], af[0], bq + 2);
                mma_bf16(acc[1][nt*2],     af[1], bq);
                mma_bf16(acc[1][nt*2 + 1], af[1], bq + 2);
            }
        }
        #pragma unroll
        for (int mt = 0; mt < 2; ++mt)
            #pragma unroll
            for (int nt = 0; nt < 8; ++nt) {
                const int r  = wm + mt*16 + (lane >> 2);
                const int cl = wnl + nt*8 + (lane & 3)*2;
                l_s[r][cl]         = acc[mt][nt][0] * 0.125f;
                l_s[r][cl + 1]     = acc[mt][nt][1] * 0.125f;
                l_s[r + 8][cl]     = acc[mt][nt][2] * 0.125f;
                l_s[r + 8][cl + 1] = acc[mt][nt][3] * 0.125f;
            }
    }
    __syncthreads();

    { // softmax: 4 lanes per row
        const int row = tid >> 2, seg = tid & 3;
        float* lr = l_s[row];
        float mx = -1e30f;
        #pragma unroll
        for (int j = 0; j < 64; ++j) mx = fmaxf(mx, lr[seg + 4*j]);
        mx = fmaxf(mx, __shfl_xor_sync(0xffffffffu, mx, 1));
        mx = fmaxf(mx, __shfl_xor_sync(0xffffffffu, mx, 2));
        float s = 0.f;
        #pragma unroll
        for (int j = 0; j < 64; ++j) {
            float e = __expf(lr[seg + 4*j] - mx);
            lr[seg + 4*j] = e;
            s += e;
        }
        s += __shfl_xor_sync(0xffffffffu, s, 1);
        s += __shfl_xor_sync(0xffffffffu, s, 2);
        const float inv = 1.f / s;
        #pragma unroll
        for (int j = 0; j < 64; ++j)
            p_s[row][seg + 4*j] = __float2bfloat16(lr[seg + 4*j] * inv);
    }
    __syncthreads();

    { // PV
        const int wn2 = (warp & 3) * 16;
        float acc2[2][2][4];
        #pragma unroll
        for (int i = 0; i < 2; i++)
            #pragma unroll
            for (int j = 0; j < 2; j++)
                #pragma unroll
                for (int q = 0; q < 4; q++) acc2[i][j][q] = 0.f;

        const unsigned pa = smaddr(&p_s[wm + (lane & 15)][(lane >> 4) * 8]);
        const unsigned va = smaddr(&v_s[lane & 15][wn2 + (lane >> 4) * 8]);

        #pragma unroll
        for (int ks = 0; ks < 16; ++ks) {
            unsigned af[2][4];
            ldsm_x4(af[0], pa + ks*32);
            ldsm_x4(af[1], pa + ks*32 + 16*528);
            unsigned bq[4];
            ldsm_x4_t(bq, va + ks*16*144);
            mma_bf16(acc2[0][0], af[0], bq);
            mma_bf16(acc2[0][1], af[0], bq + 2);
            mma_bf16(acc2[1][0], af[1], bq);
            mma_bf16(acc2[1][1], af[1], bq + 2);
        }
        #pragma unroll
        for (int mt = 0; mt < 2; ++mt)
            #pragma unroll
            for (int nt = 0; nt < 2; ++nt) {
                const int r   = wm + mt*16 + (lane >> 2);
                const int col = wn2 + nt*8 + (lane & 3)*2;
                *(bf162*)(AO + qbase + (size_t)r * 1024 + col) =
                    __floats2bfloat162_rn(acc2[mt][nt][0], acc2[mt][nt][1]);
                *(bf162*)(AO + qbase + (size_t)(r + 8) * 1024 + col) =
                    __floats2bfloat162_rn(acc2[mt][nt][2], acc2[mt][nt][3]);
            }
    }
}

// ---------------------------------------------------------------------------
extern "C" void kernel_launch(void* const* d_in, const int* in_sizes, int n_in,
                              void* d_out, int out_size)
{
    const float* h  = (const float*)d_in[0];
    const float* e  = (const float*)d_in[1];
    const float* g  = (const float*)d_in[2];
    const float* Wq = (const float*)d_in[3];
    const float* bq = (const float*)d_in[4];
    const float* Wk = (const float*)d_in[5];
    const float* bk = (const float*)d_in[6];
    const float* Wv = (const float*)d_in[7];
    const float* bv = (const float*)d_in[8];
    const float* Wo = (const float*)d_in[9];
    const float* bo = (const float*)d_in[10];
    float* out = (float*)d_out;

    cudaFuncSetAttribute(attn_bf16, cudaFuncAttributeMaxDynamicSharedMemorySize, ATTN_SMEM_BYTES);
    cudaFuncSetAttribute(gemm_cp,   cudaFuncAttributeMaxDynamicSharedMemorySize, GEMM_SMEM);

    void *p_ebf, *p_wq, *p_wkv, *p_wo, *p_hn, *p_q, *p_k, *p_v, *p_ao;
    cudaGetSymbolAddress(&p_ebf, g_ebf);
    cudaGetSymbolAddress(&p_wq,  g_wqb);
    cudaGetSymbolAddress(&p_wkv, g_wkv);
    cudaGetSymbolAddress(&p_wo,  g_wob);
    cudaGetSymbolAddress(&p_hn,  g_hnb);
    cudaGetSymbolAddress(&p_q,   g_qb);
    cudaGetSymbolAddress(&p_k,   g_kb);
    cudaGetSymbolAddress(&p_v,   g_vb);
    cudaGetSymbolAddress(&p_ao,  g_aob);

    // residual: out = h
    cudaMemcpyAsync(out, h, (size_t)4 * 1024 * 1024 * sizeof(float),
                    cudaMemcpyDeviceToDevice, 0);

    // conversions
    f2bf<<<16384, 256>>>((const float4*)e, (bf162*)p_ebf, 4194304);
    f2bf<<<1024,  256>>>((const float4*)Wq, (bf162*)p_wq, 262144);
    f2bf<<<1024,  256>>>((const float4*)Wo, (bf162*)p_wo, 262144);
    f2bf_cat<<<1024, 256>>>((const float4*)Wk, (const float4*)Wv, (bf162*)p_wkv);

    rmsnorm_bf16<<<4096, 256>>>(h, g, (bf16*)p_hn);

    // Q projection: [4096,1024] @ [1024,1024]
    gemm_cp<<<dim3(4, 32), 256, GEMM_SMEM>>>((const bf16*)p_hn, (const bf16*)p_wq,
                                             bq, bq, (bf16*)p_q, (bf16*)p_q,
                                             nullptr, 1024, 0);
    // fused K+V projection: [16384,1024] @ [1024,2048]
    gemm_cp<<<dim3(8, 128), 256, GEMM_SMEM>>>((const bf16*)p_ebf, (const bf16*)p_wkv,
                                              bk, bv, (bf16*)p_k, (bf16*)p_v,
                                              nullptr, 2048, 0);

    attn_bf16<<<1024, 256, ATTN_SMEM_BYTES>>>((const bf16*)p_q, (const bf16*)p_k,
                                              (const bf16*)p_v, (bf16*)p_ao);

    // O projection with fused +63-row shift-add
    gemm_cp<<<dim3(4, 32), 256, GEMM_SMEM>>>((const bf16*)p_ao, (const bf16*)p_wo,
                                             bo, bo, nullptr, nullptr,
                                             out, 1024, 1);
}

// round 5
// speedup vs baseline: 2.3174x; 1.0229x over previous
#include <cuda_runtime.h>
#include <cuda_bf16.h>
#include <math.h>
#include <stdint.h>

// ---------------------------------------------------------------------------
// ChunkedCrossAttention (B=4,S=1024,D=1024,H=16,Dk=64,CL=64,N=2,NL=128)
// bf16 legacy-mma pipeline; cp.async GEMM; register-softmax swizzled attention.
// ---------------------------------------------------------------------------

typedef __nv_bfloat16  bf16;
typedef __nv_bfloat162 bf162;

__device__ bf16 g_ebf[16u*1024*1024];
__device__ bf16 g_wqb[1024*1024];          // [k][n]
__device__ bf16 g_wkv[2u*1024*1024];       // [k][2048]: Wk | Wv
__device__ bf16 g_wob[1024*1024];
__device__ bf16 g_hnb[4u*1024*1024];
__device__ bf16 g_qb [4u*1024*1024];
__device__ bf16 g_kb [16u*1024*1024];
__device__ bf16 g_vb [16u*1024*1024];
__device__ bf16 g_aob[4u*1024*1024];

__device__ __forceinline__ unsigned smaddr(const void* p) {
    return (unsigned)__cvta_generic_to_shared(p);
}
__device__ __forceinline__ void cp16(uint32_t dst, const void* src) {
    asm volatile("cp.async.cg.shared.global [%0], [%1], 16;" :: "r"(dst), "l"(src));
}
#define CP_COMMIT() asm volatile("cp.async.commit_group;" ::: "memory")
#define CP_WAIT(n)  asm volatile("cp.async.wait_group %0;" :: "n"(n) : "memory")

__device__ __forceinline__ void ldsm_x4(unsigned* r, unsigned addr) {
    asm volatile("ldmatrix.sync.aligned.m8n8.x4.shared.b16 {%0,%1,%2,%3}, [%4];"
        : "=r"(r[0]), "=r"(r[1]), "=r"(r[2]), "=r"(r[3]) : "r"(addr));
}
__device__ __forceinline__ void ldsm_x4_t(unsigned* r, unsigned addr) {
    asm volatile("ldmatrix.sync.aligned.m8n8.x4.trans.shared.b16 {%0,%1,%2,%3}, [%4];"
        : "=r"(r[0]), "=r"(r[1]), "=r"(r[2]), "=r"(r[3]) : "r"(addr));
}
__device__ __forceinline__ void mma_bf16(float* c, const unsigned* a, const unsigned* b) {
    asm volatile(
        "mma.sync.aligned.m16n8k16.row.col.f32.bf16.bf16.f32 "
        "{%0,%1,%2,%3}, {%4,%5,%6,%7}, {%8,%9}, {%0,%1,%2,%3};\n"
        : "+f"(c[0]), "+f"(c[1]), "+f"(c[2]), "+f"(c[3])
        : "r"(a[0]), "r"(a[1]), "r"(a[2]), "r"(a[3]), "r"(b[0]), "r"(b[1]));
}

// ---------------------------------------------------------------------------
__global__ __launch_bounds__(256)
void f2bf(const float4* __restrict__ src, bf162* __restrict__ dst, int n4)
{
    int i = blockIdx.x * blockDim.x + threadIdx.x;
    if (i < n4) {
        float4 v = src[i];
        dst[2*i]     = __floats2bfloat162_rn(v.x, v.y);
        dst[2*i + 1] = __floats2bfloat162_rn(v.z, v.w);
    }
}

__global__ __launch_bounds__(256)
void f2bf_cat(const float4* __restrict__ srcK, const float4* __restrict__ srcV,
              bf162* __restrict__ dst)
{
    int i = blockIdx.x * blockDim.x + threadIdx.x;   // 0..262143
    int k = i >> 8, j = i & 255;
    float4 a = srcK[i], b = srcV[i];
    bf162* dk = dst + (size_t)k * 1024 + j * 2;
    dk[0] = __floats2bfloat162_rn(a.x, a.y);
    dk[1] = __floats2bfloat162_rn(a.z, a.w);
    bf162* dv = dk + 512;
    dv[0] = __floats2bfloat162_rn(b.x, b.y);
    dv[1] = __floats2bfloat162_rn(b.z, b.w);
}

// ---------------------------------------------------------------------------
__global__ __launch_bounds__(256)
void rmsnorm_bf16(const float* __restrict__ h, const float* __restrict__ g,
                  bf16* __restrict__ hn)
{
    const int row = blockIdx.x;
    const int b = row >> 10, p = row & 1023;
    const int t = threadIdx.x;
    bf162* dst = reinterpret_cast<bf162*>(hn + (size_t)row * 1024);
    if (p >= 961) {
        bf162 z = __floats2bfloat162_rn(0.f, 0.f);
        dst[2*t] = z; dst[2*t + 1] = z;
        return;
    }
    const float4* src = reinterpret_cast<const float4*>(h + ((size_t)(b*1024 + p + 63)) * 1024);
    float4 x = src[t];
    float s = x.x*x.x + x.y*x.y + x.z*x.z + x.w*x.w;
    #pragma unroll
    for (int o = 16; o; o >>= 1) s += __shfl_xor_sync(0xffffffffu, s, o);
    __shared__ float red[8];
    if ((t & 31) == 0) red[t >> 5] = s;
    __syncthreads();
    float total = red[0]+red[1]+red[2]+red[3]+red[4]+red[5]+red[6]+red[7];
    float inv = rsqrtf(total * (1.f/1024.f) + 1e-8f);
    float4 gg = reinterpret_cast<const float4*>(g)[t];
    dst[2*t]     = __floats2bfloat162_rn(x.x*gg.x*inv, x.y*gg.y*inv);
    dst[2*t + 1] = __floats2bfloat162_rn(x.z*gg.z*inv, x.w*gg.w*inv);
}

// ---------------------------------------------------------------------------
// cp.async 3-stage bf16 GEMM (unchanged from round 4; passing @ rel_err 1.2e-4).
// ---------------------------------------------------------------------------
#define GEMM_SMEM 81408

__global__ __launch_bounds__(256, 1)
void gemm_cp(const bf16* __restrict__ A, const bf16* __restrict__ Bm,
             const float* __restrict__ bias1, const float* __restrict__ bias2,
             bf16* __restrict__ C1, bf16* __restrict__ C2,
             float* __restrict__ Cf, int Nb, int mode)
{
    extern __shared__ char dyn[];
    const uint32_t sbase = smaddr(dyn);

    const int tid = threadIdx.x, lane = tid & 31, warp = tid >> 5;
    const int bm = blockIdx.y * 128, bn = blockIdx.x * 256;
    const int wm = (warp >> 2) * 64, wn = (warp & 3) * 64;

    uint32_t a_off[2]; const bf16* a_src[2];
    #pragma unroll
    for (int i = 0; i < 2; ++i) {
        int c = tid + i * 256, r = c >> 2, g = c & 3;
        a_off[i] = r * 80 + g * 16;
        a_src[i] = A + (size_t)(bm + r) * 1024 + g * 8;
    }
    uint32_t b_off[4]; const bf16* b_src[4];
    #pragma unroll
    for (int i = 0; i < 4; ++i) {
        int c = tid + i * 256, r = c >> 5, g = c & 31;
        b_off[i] = 30720 + r * 528 + g * 16;
        b_src[i] = Bm + (size_t)r * Nb + bn + g * 8;
    }

    const uint32_t aa0 = sbase + (wm + (lane & 15)) * 80 + (lane >> 4) * 16;
    const uint32_t ba0 = sbase + 30720 + (lane & 15) * 528 + (wn + (lane >> 4) * 8) * 2;

    float acc[4][8][4];
    #pragma unroll
    for (int a = 0; a < 4; ++a)
        #pragma unroll
        for (int b = 0; b < 8; ++b)
            #pragma unroll
            for (int q = 0; q < 4; ++q) acc[a][b][q] = 0.f;

    #pragma unroll
    for (int s = 0; s < 2; ++s) {
        #pragma unroll
        for (int i = 0; i < 2; ++i) cp16(sbase + s*10240 + a_off[i], a_src[i] + s*32);
        #pragma unroll
        for (int i = 0; i < 4; ++i) cp16(sbase + s*16896 + b_off[i], b_src[i] + (size_t)s*32*Nb);
        CP_COMMIT();
    }
    CP_WAIT(1);
    __syncthreads();

    for (int kt = 0; kt < 32; ++kt) {
        const int stg = kt - (kt >= 3 ? 3 * ((kt * 0x5556) >> 16) : 0);
        const uint32_t aa = aa0 + stg * 10240;
        const uint32_t ba = ba0 + stg * 16896;
        #pragma unroll
        for (int ks = 0; ks < 2; ++ks) {
            unsigned af[4][4];
            #pragma unroll
            for (int mt = 0; mt < 4; ++mt) ldsm_x4(af[mt], aa + mt*1280 + ks*32);
            unsigned bq[4][4];
            #pragma unroll
            for (int nt = 0; nt < 4; ++nt) ldsm_x4_t(bq[nt], ba + ks*8448 + nt*32);
            #pragma unroll
            for (int mt = 0; mt < 4; ++mt)
                #pragma unroll
                for (int nt = 0; nt < 4; ++nt) {
                    mma_bf16(acc[mt][nt*2],     af[mt], bq[nt]);
                    mma_bf16(acc[mt][nt*2 + 1], af[mt], bq[nt] + 2);
                }
        }
        if (kt == 31) break;
        if (kt + 2 < 32) {
            const int ns = (kt + 2) - 3 * ((kt + 2) / 3);
            #pragma unroll
            for (int i = 0; i < 2; ++i)
                cp16(sbase + ns*10240 + a_off[i], a_src[i] + (kt + 2) * 32);
            #pragma unroll
            for (int i = 0; i < 4; ++i)
                cp16(sbase + ns*16896 + b_off[i], b_src[i] + (size_t)(kt + 2)*32*Nb);
            CP_COMMIT();
            CP_WAIT(1);
        } else {
            CP_WAIT(0);
        }
        __syncthreads();
    }

    #pragma unroll
    for (int mt = 0; mt < 4; ++mt) {
        #pragma unroll
        for (int j = 0; j < 8; ++j) {
            const int row  = bm + wm + mt * 16 + (lane >> 2);
            const int gcol = bn + wn + j * 8 + (lane & 3) * 2;
            if (mode == 0) {
                const float* bb = bias1; bf16* dst = C1; int cc = gcol;
                if (gcol >= 1024) { bb = bias2; dst = C2; cc = gcol - 1024; }
                const float b0 = bb[cc], b1 = bb[cc + 1];
                *(bf162*)(dst + (size_t)row * 1024 + cc) =
                    __floats2bfloat162_rn(acc[mt][j][0] + b0, acc[mt][j][1] + b1);
                *(bf162*)(dst + (size_t)(row + 8) * 1024 + cc) =
                    __floats2bfloat162_rn(acc[mt][j][2] + b0, acc[mt][j][3] + b1);
            } else {
                const float b0 = bias1[gcol], b1 = bias1[gcol + 1];
                const int p = row & 1023;
                if (p < 961) {
                    float* o = Cf + (size_t)(row + 63) * 1024 + gcol;
                    o[0] += acc[mt][j][0] + b0;
                    o[1] += acc[mt][j][1] + b1;
                }
                const int p2 = (row + 8) & 1023;
                if (p2 < 961) {
                    float* o = Cf + (size_t)(row + 71) * 1024 + gcol;
                    o[0] += acc[mt][j][2] + b0;
                    o[1] += acc[mt][j][3] + b1;
                }
            }
        }
    }
}

// ---------------------------------------------------------------------------
// Attention per (b, chunk, head): 256 threads = 8 warps (2m x 4n).
// Register-resident logits + distributed softmax; swizzled unpadded smem
// (16B-group index XOR (row&7)) -> conflict-free ldmatrix, 106KB => 2 CTA/SM.
// smem: q 8192 @0 | k 32768 @8192 | v 32768 @40960 | p 32768 @73728
//       red_max 1024 @106496 | red_sum 1024 @107520  -> total 108544
// ---------------------------------------------------------------------------
#define ATTN_SMEM_BYTES 108544

__global__ __launch_bounds__(256, 2)
void attn_bf16(const bf16* __restrict__ Q, const bf16* __restrict__ K,
               const bf16* __restrict__ V, bf16* __restrict__ AO)
{
    extern __shared__ char smraw[];
    const uint32_t sb = smaddr(smraw);
    const uint32_t qb = sb, kb = sb + 8192, vb = sb + 40960, pb = sb + 73728;
    float* red_max = reinterpret_cast<float*>(smraw + 106496);   // [4][64]
    float* red_sum = reinterpret_cast<float*>(smraw + 107520);   // [4][64]

    const int bid = blockIdx.x;
    const int b  = bid >> 8, c = (bid >> 4) & 15, hh = bid & 15;
    const int tid = threadIdx.x, lane = tid & 31, warp = tid >> 5;

    const size_t qbase  = ((size_t)(b * 1024 + c * 64)) * 1024 + hh * 64;
    const size_t kvbase = ((size_t)((b * 16 + c) * 256)) * 1024 + hh * 64;

    // ---- gmem -> swizzled smem ----
    #pragma unroll
    for (int i = 0; i < 2; ++i) {
        int ch = tid + i * 256, r = ch >> 3, sg = ch & 7;
        uint32_t off = r * 128 + (((uint32_t)sg << 4) ^ (((uint32_t)(r & 7)) << 4));
        *(uint4*)(smraw + off) = *(const uint4*)(Q + qbase + (size_t)r * 1024 + sg * 8);
    }
    #pragma unroll
    for (int i = 0; i < 8; ++i) {
        int ch = tid + i * 256, r = ch >> 3, sg = ch & 7;
        uint32_t off = r * 128 + (((uint32_t)sg << 4) ^ (((uint32_t)(r & 7)) << 4));
        *(uint4*)(smraw + 8192 + off)  = *(const uint4*)(K + kvbase + (size_t)r * 1024 + sg * 8);
        *(uint4*)(smraw + 40960 + off) = *(const uint4*)(V + kvbase + (size_t)r * 1024 + sg * 8);
    }
    __syncthreads();

    const int wm  = (warp >> 2) * 32;
    const uint32_t xr = ((uint32_t)(lane & 7)) << 4;

    // ---- logits in registers: warp tile 32 x 64 ----
    float acc[2][8][4];
    #pragma unroll
    for (int i = 0; i < 2; i++)
        #pragma unroll
        for (int j = 0; j < 8; j++)
            #pragma unroll
            for (int q = 0; q < 4; q++) acc[i][j][q] = 0.f;

    {
        const int wnl = (warp & 3) * 64;
        const uint32_t qrow = qb + (wm + (lane & 15)) * 128;
        const uint32_t krow = kb + (wnl + (lane & 7) + ((lane >> 4) & 1) * 8) * 128;

        #pragma unroll
        for (int ks = 0; ks < 4; ++ks) {
            const uint32_t gq = (uint32_t)((lane >> 4) + ks * 2) << 4;
            unsigned af[2][4];
            ldsm_x4(af[0], qrow + (gq ^ xr));
            ldsm_x4(af[1], qrow + 16*128 + (gq ^ xr));
            const uint32_t gk = (uint32_t)(((lane >> 3) & 1) + ks * 2) << 4;
            #pragma unroll
            for (int nt = 0; nt < 4; ++nt) {
                unsigned bq[4];
                ldsm_x4(bq, krow + nt*16*128 + (gk ^ xr));
                mma_bf16(acc[0][nt*2],     af[0], bq);
                mma_bf16(acc[0][nt*2 + 1], af[0], bq + 2);
                mma_bf16(acc[1][nt*2],     af[1], bq);
                mma_bf16(acc[1][nt*2 + 1], af[1], bq + 2);
            }
        }
    }

    // ---- softmax over registers ----
    #pragma unroll
    for (int i = 0; i < 2; i++)
        #pragma unroll
        for (int j = 0; j < 8; j++)
            #pragma unroll
            for (int q = 0; q < 4; q++) acc[i][j][q] *= 0.125f;

    const int rloc0 = wm + (lane >> 2);   // +mt*16 +hf*8
    { // partial max
        #pragma unroll
        for (int mt = 0; mt < 2; ++mt)
            #pragma unroll
            for (int hf = 0; hf < 2; ++hf) {
                float m = -1e30f;
                #pragma unroll
                for (int nt = 0; nt < 8; ++nt)
                    m = fmaxf(m, fmaxf(acc[mt][nt][hf*2], acc[mt][nt][hf*2 + 1]));
                m = fmaxf(m, __shfl_xor_sync(0xffffffffu, m, 1));
                m = fmaxf(m, __shfl_xor_sync(0xffffffffu, m, 2));
                if ((lane & 3) == 0)
                    red_max[(warp & 3) * 64 + rloc0 + mt*16 + hf*8] = m;
            }
    }
    __syncthreads();
    { // exp + partial sum
        #pragma unroll
        for (int mt = 0; mt < 2; ++mt)
            #pragma unroll
            for (int hf = 0; hf < 2; ++hf) {
                const int row = rloc0 + mt*16 + hf*8;
                const float gm = fmaxf(fmaxf(red_max[row], red_max[64 + row]),
                                       fmaxf(red_max[128 + row], red_max[192 + row]));
                float s = 0.f;
                #pragma unroll
                for (int nt = 0; nt < 8; ++nt) {
                    float e0 = __expf(acc[mt][nt][hf*2]     - gm);
                    float e1 = __expf(acc[mt][nt][hf*2 + 1] - gm);
                    acc[mt][nt][hf*2] = e0; acc[mt][nt][hf*2 + 1] = e1;
                    s += e0 + e1;
                }
                s += __shfl_xor_sync(0xffffffffu, s, 1);
                s += __shfl_xor_sync(0xffffffffu, s, 2);
                if ((lane & 3) == 0)
                    red_sum[(warp & 3) * 64 + row] = s;
            }
    }
    __syncthreads();
    { // normalize + write P (swizzled bf16)
        #pragma unroll
        for (int mt = 0; mt < 2; ++mt)
            #pragma unroll
            for (int hf = 0; hf < 2; ++hf) {
                const int row = rloc0 + mt*16 + hf*8;
                const float gs = red_sum[row] + red_sum[64 + row] +
                                 red_sum[128 + row] + red_sum[192 + row];
                const float inv = 1.f / gs;
                #pragma unroll
                for (int nt = 0; nt < 8; ++nt) {
                    const uint32_t g = 8 * (warp & 3) + nt;
                    const uint32_t off = row * 512 + ((g << 4) ^ (((uint32_t)(row & 7)) << 4))
                                       + (lane & 3) * 4;
                    *(bf162*)(smraw + 73728 + off) =
                        __floats2bfloat162_rn(acc[mt][nt][hf*2] * inv,
                                              acc[mt][nt][hf*2 + 1] * inv);
                }
            }
    }
    __syncthreads();

    // ---- PV: warp tile 32 x 16, k = 256 ----
    {
        const int wn2 = (warp & 3) * 16;
        float acc2[2][2][4];
        #pragma unroll
        for (int i = 0; i < 2; i++)
            #pragma unroll
            for (int j = 0; j < 2; j++)
                #pragma unroll
                for (int q = 0; q < 4; q++) acc2[i][j][q] = 0.f;

        const uint32_t prow  = pb + (wm + (lane & 15)) * 512;
        const uint32_t vrow0 = vb + (lane & 15) * 128;
        const uint32_t gv = ((uint32_t)(2 * (warp & 3) + (lane >> 4))) << 4;

        #pragma unroll
        for (int ks = 0; ks < 16; ++ks) {
            const uint32_t gp = (uint32_t)((lane >> 4) + ks * 2) << 4;
            unsigned af[2][4];
            ldsm_x4(af[0], prow + (gp ^ xr));
            ldsm_x4(af[1], prow + 16*512 + (gp ^ xr));
            unsigned bq[4];
            ldsm_x4_t(bq, vrow0 + ks*16*128 + (gv ^ xr));
            mma_bf16(acc2[0][0], af[0], bq);
            mma_bf16(acc2[0][1], af[0], bq + 2);
            mma_bf16(acc2[1][0], af[1], bq);
            mma_bf16(acc2[1][1], af[1], bq + 2);
        }
        #pragma unroll
        for (int mt = 0; mt < 2; ++mt)
            #pragma unroll
            for (int nt = 0; nt < 2; ++nt) {
                const int r   = wm + mt*16 + (lane >> 2);
                const int col = wn2 + nt*8 + (lane & 3)*2;
                *(bf162*)(AO + qbase + (size_t)r * 1024 + col) =
                    __floats2bfloat162_rn(acc2[mt][nt][0], acc2[mt][nt][1]);
                *(bf162*)(AO + qbase + (size_t)(r + 8) * 1024 + col) =
                    __floats2bfloat162_rn(acc2[mt][nt][2], acc2[mt][nt][3]);
            }
    }
}

// ---------------------------------------------------------------------------
extern "C" void kernel_launch(void* const* d_in, const int* in_sizes, int n_in,
                              void* d_out, int out_size)
{
    const float* h  = (const float*)d_in[0];
    const float* e  = (const float*)d_in[1];
    const float* g  = (const float*)d_in[2];
    const float* Wq = (const float*)d_in[3];
    const float* bq = (const float*)d_in[4];
    const float* Wk = (const float*)d_in[5];
    const float* bk = (const float*)d_in[6];
    const float* Wv = (const float*)d_in[7];
    const float* bv = (const float*)d_in[8];
    const float* Wo = (const float*)d_in[9];
    const float* bo = (const float*)d_in[10];
    float* out = (float*)d_out;

    cudaFuncSetAttribute(attn_bf16, cudaFuncAttributeMaxDynamicSharedMemorySize, ATTN_SMEM_BYTES);
    cudaFuncSetAttribute(gemm_cp,   cudaFuncAttributeMaxDynamicSharedMemorySize, GEMM_SMEM);

    void *p_ebf, *p_wq, *p_wkv, *p_wo, *p_hn, *p_q, *p_k, *p_v, *p_ao;
    cudaGetSymbolAddress(&p_ebf, g_ebf);
    cudaGetSymbolAddress(&p_wq,  g_wqb);
    cudaGetSymbolAddress(&p_wkv, g_wkv);
    cudaGetSymbolAddress(&p_wo,  g_wob);
    cudaGetSymbolAddress(&p_hn,  g_hnb);
    cudaGetSymbolAddress(&p_q,   g_qb);
    cudaGetSymbolAddress(&p_k,   g_kb);
    cudaGetSymbolAddress(&p_v,   g_vb);
    cudaGetSymbolAddress(&p_ao,  g_aob);

    // node 1: residual out = h
    cudaMemcpyAsync(out, h, (size_t)4 * 1024 * 1024 * sizeof(float),
                    cudaMemcpyDeviceToDevice, 0);

    // nodes 2-4
    f2bf<<<16384, 256>>>((const float4*)e, (bf162*)p_ebf, 4194304);
    f2bf_cat<<<1024, 256>>>((const float4*)Wk, (const float4*)Wv, (bf162*)p_wkv);
    rmsnorm_bf16<<<4096, 256>>>(h, g, (bf16*)p_hn);

    // node 5 (profiled next round): fused K+V projection [16384,1024]@[1024,2048]
    gemm_cp<<<dim3(8, 128), 256, GEMM_SMEM>>>((const bf16*)p_ebf, (const bf16*)p_wkv,
                                              bk, bv, (bf16*)p_k, (bf16*)p_v,
                                              nullptr, 2048, 0);

    // remaining conversions + Q projection
    f2bf<<<1024, 256>>>((const float4*)Wq, (bf162*)p_wq, 262144);
    f2bf<<<1024, 256>>>((const float4*)Wo, (bf162*)p_wo, 262144);
    gemm_cp<<<dim3(4, 32), 256, GEMM_SMEM>>>((const bf16*)p_hn, (const bf16*)p_wq,
                                             bq, bq, (bf16*)p_q, (bf16*)p_q,
                                             nullptr, 1024, 0);

    attn_bf16<<<1024, 256, ATTN_SMEM_BYTES>>>((const bf16*)p_q, (const bf16*)p_k,
                                              (const bf16*)p_v, (bf16*)p_ao);

    // O projection with fused +63-row shift-add
    gemm_cp<<<dim3(4, 32), 256, GEMM_SMEM>>>((const bf16*)p_ao, (const bf16*)p_wo,
                                             bo, bo, nullptr, nullptr,
                                             out, 1024, 1);
}

// round 6
// speedup vs baseline: 2.5949x; 1.1198x over previous
#include <cuda_runtime.h>
#include <cuda_bf16.h>
#include <math.h>
#include <stdint.h>

// ---------------------------------------------------------------------------
// ChunkedCrossAttention (B=4,S=1024,D=1024,H=16,Dk=64,CL=64,N=2,NL=128)
// bf16 legacy-mma pipeline; 512-thread 4-stage cp.async GEMM; reg-softmax attn.
// ---------------------------------------------------------------------------

typedef __nv_bfloat16  bf16;
typedef __nv_bfloat162 bf162;

__device__ bf16 g_ebf[16u*1024*1024];
__device__ bf16 g_wqb[1024*1024];          // [k][n]
__device__ bf16 g_wkv[2u*1024*1024];       // [k][2048]: Wk | Wv
__device__ bf16 g_wob[1024*1024];
__device__ bf16 g_hnb[4u*1024*1024];
__device__ bf16 g_qb [4u*1024*1024];
__device__ bf16 g_kb [16u*1024*1024];
__device__ bf16 g_vb [16u*1024*1024];
__device__ bf16 g_aob[4u*1024*1024];

__device__ __forceinline__ unsigned smaddr(const void* p) {
    return (unsigned)__cvta_generic_to_shared(p);
}
__device__ __forceinline__ void cp16(uint32_t dst, const void* src) {
    asm volatile("cp.async.cg.shared.global [%0], [%1], 16;" :: "r"(dst), "l"(src));
}
#define CP_COMMIT() asm volatile("cp.async.commit_group;" ::: "memory")
#define CP_WAIT(n)  asm volatile("cp.async.wait_group %0;" :: "n"(n) : "memory")

__device__ __forceinline__ void ldsm_x4(unsigned* r, unsigned addr) {
    asm volatile("ldmatrix.sync.aligned.m8n8.x4.shared.b16 {%0,%1,%2,%3}, [%4];"
        : "=r"(r[0]), "=r"(r[1]), "=r"(r[2]), "=r"(r[3]) : "r"(addr));
}
__device__ __forceinline__ void ldsm_x4_t(unsigned* r, unsigned addr) {
    asm volatile("ldmatrix.sync.aligned.m8n8.x4.trans.shared.b16 {%0,%1,%2,%3}, [%4];"
        : "=r"(r[0]), "=r"(r[1]), "=r"(r[2]), "=r"(r[3]) : "r"(addr));
}
__device__ __forceinline__ void mma_bf16(float* c, const unsigned* a, const unsigned* b) {
    asm volatile(
        "mma.sync.aligned.m16n8k16.row.col.f32.bf16.bf16.f32 "
        "{%0,%1,%2,%3}, {%4,%5,%6,%7}, {%8,%9}, {%0,%1,%2,%3};\n"
        : "+f"(c[0]), "+f"(c[1]), "+f"(c[2]), "+f"(c[3])
        : "r"(a[0]), "r"(a[1]), "r"(a[2]), "r"(a[3]), "r"(b[0]), "r"(b[1]));
}

// ---------------------------------------------------------------------------
__global__ __launch_bounds__(256)
void f2bf(const float4* __restrict__ src, bf162* __restrict__ dst, int n4)
{
    int i = blockIdx.x * blockDim.x + threadIdx.x;
    if (i < n4) {
        float4 v = src[i];
        dst[2*i]     = __floats2bfloat162_rn(v.x, v.y);
        dst[2*i + 1] = __floats2bfloat162_rn(v.z, v.w);
    }
}

__global__ __launch_bounds__(256)
void f2bf_cat(const float4* __restrict__ srcK, const float4* __restrict__ srcV,
              bf162* __restrict__ dst)
{
    int i = blockIdx.x * blockDim.x + threadIdx.x;   // 0..262143
    int k = i >> 8, j = i & 255;
    float4 a = srcK[i], b = srcV[i];
    bf162* dk = dst + (size_t)k * 1024 + j * 2;
    dk[0] = __floats2bfloat162_rn(a.x, a.y);
    dk[1] = __floats2bfloat162_rn(a.z, a.w);
    bf162* dv = dk + 512;
    dv[0] = __floats2bfloat162_rn(b.x, b.y);
    dv[1] = __floats2bfloat162_rn(b.z, b.w);
}

// ---------------------------------------------------------------------------
__global__ __launch_bounds__(256)
void rmsnorm_bf16(const float* __restrict__ h, const float* __restrict__ g,
                  bf16* __restrict__ hn)
{
    const int row = blockIdx.x;
    const int b = row >> 10, p = row & 1023;
    const int t = threadIdx.x;
    bf162* dst = reinterpret_cast<bf162*>(hn + (size_t)row * 1024);
    if (p >= 961) {
        bf162 z = __floats2bfloat162_rn(0.f, 0.f);
        dst[2*t] = z; dst[2*t + 1] = z;
        return;
    }
    const float4* src = reinterpret_cast<const float4*>(h + ((size_t)(b*1024 + p + 63)) * 1024);
    float4 x = src[t];
    float s = x.x*x.x + x.y*x.y + x.z*x.z + x.w*x.w;
    #pragma unroll
    for (int o = 16; o; o >>= 1) s += __shfl_xor_sync(0xffffffffu, s, o);
    __shared__ float red[8];
    if ((t & 31) == 0) red[t >> 5] = s;
    __syncthreads();
    float total = red[0]+red[1]+red[2]+red[3]+red[4]+red[5]+red[6]+red[7];
    float inv = rsqrtf(total * (1.f/1024.f) + 1e-8f);
    float4 gg = reinterpret_cast<const float4*>(g)[t];
    dst[2*t]     = __floats2bfloat162_rn(x.x*gg.x*inv, x.y*gg.y*inv);
    dst[2*t + 1] = __floats2bfloat162_rn(x.z*gg.z*inv, x.w*gg.w*inv);
}

// ---------------------------------------------------------------------------
// 512-thread 4-stage cp.async bf16 GEMM. Tile 128x256, BK=32,
// 16 warps (4m x 4n), warp tile 32x64 (64 acc regs -> no spills).
// B is [k][Nb] row-major. mode 0: split store (cols<1024 -> C1, else C2).
// mode 1: fp32 shift-add (+63 rows, p<961) into Cf with bias1.
// smem/stage: A 10240 (stride 80) + B 16896 (stride 528); 4 stages = 108544.
// ---------------------------------------------------------------------------
#define GEMM_SMEM (4 * (10240 + 16896))

__global__ __launch_bounds__(512, 1)
void gemm_cp(const bf16* __restrict__ A, const bf16* __restrict__ Bm,
             const float* __restrict__ bias1, const float* __restrict__ bias2,
             bf16* __restrict__ C1, bf16* __restrict__ C2,
             float* __restrict__ Cf, int Nb, int mode)
{
    extern __shared__ char dyn[];
    const uint32_t sbase = smaddr(dyn);
    const uint32_t STG = 10240 + 16896;   // 27136

    const int tid = threadIdx.x, lane = tid & 31, warp = tid >> 5;
    const int bm = blockIdx.y * 128, bn = blockIdx.x * 256;
    const int wm = (warp >> 2) * 32, wn = (warp & 3) * 64;

    // A: 512 chunks/stage (1 per thread); B: 1024 chunks/stage (2 per thread)
    const uint32_t a_off = (tid >> 2) * 80 + (tid & 3) * 16;
    const bf16* a_src = A + (size_t)(bm + (tid >> 2)) * 1024 + (tid & 3) * 8;
    uint32_t b_off[2]; const bf16* b_src[2];
    #pragma unroll
    for (int i = 0; i < 2; ++i) {
        int c = tid + i * 512, r = c >> 5, g = c & 31;
        b_off[i] = 10240 + r * 528 + g * 16;
        b_src[i] = Bm + (size_t)r * Nb + bn + g * 8;
    }

    const uint32_t aa0 = sbase + (wm + (lane & 15)) * 80 + (lane >> 4) * 16;
    const uint32_t ba0 = sbase + 10240 + (lane & 15) * 528 + (wn + (lane >> 4) * 8) * 2;

    float acc[2][8][4];
    #pragma unroll
    for (int a = 0; a < 2; ++a)
        #pragma unroll
        for (int b = 0; b < 8; ++b)
            #pragma unroll
            for (int q = 0; q < 4; ++q) acc[a][b][q] = 0.f;

    // prologue: stages 0..2
    #pragma unroll
    for (int s = 0; s < 3; ++s) {
        cp16(sbase + s*STG + a_off, a_src + s*32);
        #pragma unroll
        for (int i = 0; i < 2; ++i)
            cp16(sbase + s*STG + b_off[i], b_src[i] + (size_t)s*32*Nb);
        CP_COMMIT();
    }
    CP_WAIT(2);
    __syncthreads();

    for (int kt = 0; kt < 32; ++kt) {
        const int stg = kt & 3;
        const uint32_t aa = aa0 + stg * STG;
        const uint32_t ba = ba0 + stg * STG;
        #pragma unroll
        for (int ks = 0; ks < 2; ++ks) {
            unsigned af[2][4];
            #pragma unroll
            for (int mt = 0; mt < 2; ++mt) ldsm_x4(af[mt], aa + mt*1280 + ks*32);
            unsigned bq[4][4];
            #pragma unroll
            for (int nt = 0; nt < 4; ++nt) ldsm_x4_t(bq[nt], ba + ks*8448 + nt*32);
            #pragma unroll
            for (int mt = 0; mt < 2; ++mt)
                #pragma unroll
                for (int nt = 0; nt < 4; ++nt) {
                    mma_bf16(acc[mt][nt*2],     af[mt], bq[nt]);
                    mma_bf16(acc[mt][nt*2 + 1], af[mt], bq[nt] + 2);
                }
        }
        if (kt == 31) break;
        if (kt + 3 < 32) {
            const int ns = (kt + 3) & 3;
            cp16(sbase + ns*STG + a_off, a_src + (kt + 3) * 32);
            #pragma unroll
            for (int i = 0; i < 2; ++i)
                cp16(sbase + ns*STG + b_off[i], b_src[i] + (size_t)(kt + 3)*32*Nb);
        }
        CP_COMMIT();
        CP_WAIT(2);
        __syncthreads();
    }

    // ---- epilogue ----
    #pragma unroll
    for (int mt = 0; mt < 2; ++mt) {
        #pragma unroll
        for (int j = 0; j < 8; ++j) {
            const int row  = bm + wm + mt * 16 + (lane >> 2);
            const int gcol = bn + wn + j * 8 + (lane & 3) * 2;
            if (mode == 0) {
                const float* bb = bias1; bf16* dst = C1; int cc = gcol;
                if (gcol >= 1024) { bb = bias2; dst = C2; cc = gcol - 1024; }
                const float b0 = bb[cc], b1 = bb[cc + 1];
                *(bf162*)(dst + (size_t)row * 1024 + cc) =
                    __floats2bfloat162_rn(acc[mt][j][0] + b0, acc[mt][j][1] + b1);
                *(bf162*)(dst + (size_t)(row + 8) * 1024 + cc) =
                    __floats2bfloat162_rn(acc[mt][j][2] + b0, acc[mt][j][3] + b1);
            } else {
                const float b0 = bias1[gcol], b1 = bias1[gcol + 1];
                const int p = row & 1023;
                if (p < 961) {
                    float* o = Cf + (size_t)(row + 63) * 1024 + gcol;
                    o[0] += acc[mt][j][0] + b0;
                    o[1] += acc[mt][j][1] + b1;
                }
                const int p2 = (row + 8) & 1023;
                if (p2 < 961) {
                    float* o = Cf + (size_t)(row + 71) * 1024 + gcol;
                    o[0] += acc[mt][j][2] + b0;
                    o[1] += acc[mt][j][3] + b1;
                }
            }
        }
    }
}

// ---------------------------------------------------------------------------
// Attention per (b, chunk, head): 256 threads = 8 warps (2m x 4n).
// Register-resident logits + distributed softmax; swizzled unpadded smem.
// ---------------------------------------------------------------------------
#define ATTN_SMEM_BYTES 108544

__global__ __launch_bounds__(256, 2)
void attn_bf16(const bf16* __restrict__ Q, const bf16* __restrict__ K,
               const bf16* __restrict__ V, bf16* __restrict__ AO)
{
    extern __shared__ char smraw[];
    const uint32_t sb = smaddr(smraw);
    const uint32_t qb = sb, kb = sb + 8192, vb = sb + 40960, pb = sb + 73728;
    float* red_max = reinterpret_cast<float*>(smraw + 106496);   // [4][64]
    float* red_sum = reinterpret_cast<float*>(smraw + 107520);   // [4][64]

    const int bid = blockIdx.x;
    const int b  = bid >> 8, c = (bid >> 4) & 15, hh = bid & 15;
    const int tid = threadIdx.x, lane = tid & 31, warp = tid >> 5;

    const size_t qbase  = ((size_t)(b * 1024 + c * 64)) * 1024 + hh * 64;
    const size_t kvbase = ((size_t)((b * 16 + c) * 256)) * 1024 + hh * 64;

    #pragma unroll
    for (int i = 0; i < 2; ++i) {
        int ch = tid + i * 256, r = ch >> 3, sg = ch & 7;
        uint32_t off = r * 128 + (((uint32_t)sg << 4) ^ (((uint32_t)(r & 7)) << 4));
        *(uint4*)(smraw + off) = *(const uint4*)(Q + qbase + (size_t)r * 1024 + sg * 8);
    }
    #pragma unroll
    for (int i = 0; i < 8; ++i) {
        int ch = tid + i * 256, r = ch >> 3, sg = ch & 7;
        uint32_t off = r * 128 + (((uint32_t)sg << 4) ^ (((uint32_t)(r & 7)) << 4));
        *(uint4*)(smraw + 8192 + off)  = *(const uint4*)(K + kvbase + (size_t)r * 1024 + sg * 8);
        *(uint4*)(smraw + 40960 + off) = *(const uint4*)(V + kvbase + (size_t)r * 1024 + sg * 8);
    }
    __syncthreads();

    const int wm  = (warp >> 2) * 32;
    const uint32_t xr = ((uint32_t)(lane & 7)) << 4;

    float acc[2][8][4];
    #pragma unroll
    for (int i = 0; i < 2; i++)
        #pragma unroll
        for (int j = 0; j < 8; j++)
            #pragma unroll
            for (int q = 0; q < 4; q++) acc[i][j][q] = 0.f;

    {
        const int wnl = (warp & 3) * 64;
        const uint32_t qrow = qb + (wm + (lane & 15)) * 128;
        const uint32_t krow = kb + (wnl + (lane & 7) + ((lane >> 4) & 1) * 8) * 128;

        #pragma unroll
        for (int ks = 0; ks < 4; ++ks) {
            const uint32_t gq = (uint32_t)((lane >> 4) + ks * 2) << 4;
            unsigned af[2][4];
            ldsm_x4(af[0], qrow + (gq ^ xr));
            ldsm_x4(af[1], qrow + 16*128 + (gq ^ xr));
            const uint32_t gk = (uint32_t)(((lane >> 3) & 1) + ks * 2) << 4;
            #pragma unroll
            for (int nt = 0; nt < 4; ++nt) {
                unsigned bq[4];
                ldsm_x4(bq, krow + nt*16*128 + (gk ^ xr));
                mma_bf16(acc[0][nt*2],     af[0], bq);
                mma_bf16(acc[0][nt*2 + 1], af[0], bq + 2);
                mma_bf16(acc[1][nt*2],     af[1], bq);
                mma_bf16(acc[1][nt*2 + 1], af[1], bq + 2);
            }
        }
    }

    #pragma unroll
    for (int i = 0; i < 2; i++)
        #pragma unroll
        for (int j = 0; j < 8; j++)
            #pragma unroll
            for (int q = 0; q < 4; q++) acc[i][j][q] *= 0.125f;

    const int rloc0 = wm + (lane >> 2);
    {
        #pragma unroll
        for (int mt = 0; mt < 2; ++mt)
            #pragma unroll
            for (int hf = 0; hf < 2; ++hf) {
                float m = -1e30f;
                #pragma unroll
                for (int nt = 0; nt < 8; ++nt)
                    m = fmaxf(m, fmaxf(acc[mt][nt][hf*2], acc[mt][nt][hf*2 + 1]));
                m = fmaxf(m, __shfl_xor_sync(0xffffffffu, m, 1));
                m = fmaxf(m, __shfl_xor_sync(0xffffffffu, m, 2));
                if ((lane & 3) == 0)
                    red_max[(warp & 3) * 64 + rloc0 + mt*16 + hf*8] = m;
            }
    }
    __syncthreads();
    {
        #pragma unroll
        for (int mt = 0; mt < 2; ++mt)
            #pragma unroll
            for (int hf = 0; hf < 2; ++hf) {
                const int row = rloc0 + mt*16 + hf*8;
                const float gm = fmaxf(fmaxf(red_max[row], red_max[64 + row]),
                                       fmaxf(red_max[128 + row], red_max[192 + row]));
                float s = 0.f;
                #pragma unroll
                for (int nt = 0; nt < 8; ++nt) {
                    float e0 = __expf(acc[mt][nt][hf*2]     - gm);
                    float e1 = __expf(acc[mt][nt][hf*2 + 1] - gm);
                    acc[mt][nt][hf*2] = e0; acc[mt][nt][hf*2 + 1] = e1;
                    s += e0 + e1;
                }
                s += __shfl_xor_sync(0xffffffffu, s, 1);
                s += __shfl_xor_sync(0xffffffffu, s, 2);
                if ((lane & 3) == 0)
                    red_sum[(warp & 3) * 64 + row] = s;
            }
    }
    __syncthreads();
    {
        #pragma unroll
        for (int mt = 0; mt < 2; ++mt)
            #pragma unroll
            for (int hf = 0; hf < 2; ++hf) {
                const int row = rloc0 + mt*16 + hf*8;
                const float gs = red_sum[row] + red_sum[64 + row] +
                                 red_sum[128 + row] + red_sum[192 + row];
                const float inv = 1.f / gs;
                #pragma unroll
                for (int nt = 0; nt < 8; ++nt) {
                    const uint32_t g = 8 * (warp & 3) + nt;
                    const uint32_t off = row * 512 + ((g << 4) ^ (((uint32_t)(row & 7)) << 4))
                                       + (lane & 3) * 4;
                    *(bf162*)(smraw + 73728 + off) =
                        __floats2bfloat162_rn(acc[mt][nt][hf*2] * inv,
                                              acc[mt][nt][hf*2 + 1] * inv);
                }
            }
    }
    __syncthreads();

    {
        const int wn2 = (warp & 3) * 16;
        float acc2[2][2][4];
        #pragma unroll
        for (int i = 0; i < 2; i++)
            #pragma unroll
            for (int j = 0; j < 2; j++)
                #pragma unroll
                for (int q = 0; q < 4; q++) acc2[i][j][q] = 0.f;

        const uint32_t prow  = pb + (wm + (lane & 15)) * 512;
        const uint32_t vrow0 = vb + (lane & 15) * 128;
        const uint32_t gv = ((uint32_t)(2 * (warp & 3) + (lane >> 4))) << 4;

        #pragma unroll
        for (int ks = 0; ks < 16; ++ks) {
            const uint32_t gp = (uint32_t)((lane >> 4) + ks * 2) << 4;
            unsigned af[2][4];
            ldsm_x4(af[0], prow + (gp ^ xr));
            ldsm_x4(af[1], prow + 16*512 + (gp ^ xr));
            unsigned bq[4];
            ldsm_x4_t(bq, vrow0 + ks*16*128 + (gv ^ xr));
            mma_bf16(acc2[0][0], af[0], bq);
            mma_bf16(acc2[0][1], af[0], bq + 2);
            mma_bf16(acc2[1][0], af[1], bq);
            mma_bf16(acc2[1][1], af[1], bq + 2);
        }
        #pragma unroll
        for (int mt = 0; mt < 2; ++mt)
            #pragma unroll
            for (int nt = 0; nt < 2; ++nt) {
                const int r   = wm + mt*16 + (lane >> 2);
                const int col = wn2 + nt*8 + (lane & 3)*2;
                *(bf162*)(AO + qbase + (size_t)r * 1024 + col) =
                    __floats2bfloat162_rn(acc2[mt][nt][0], acc2[mt][nt][1]);
                *(bf162*)(AO + qbase + (size_t)(r + 8) * 1024 + col) =
                    __floats2bfloat162_rn(acc2[mt][nt][2], acc2[mt][nt][3]);
            }
    }
}

// ---------------------------------------------------------------------------
extern "C" void kernel_launch(void* const* d_in, const int* in_sizes, int n_in,
                              void* d_out, int out_size)
{
    const float* h  = (const float*)d_in[0];
    const float* e  = (const float*)d_in[1];
    const float* g  = (const float*)d_in[2];
    const float* Wq = (const float*)d_in[3];
    const float* bq = (const float*)d_in[4];
    const float* Wk = (const float*)d_in[5];
    const float* bk = (const float*)d_in[6];
    const float* Wv = (const float*)d_in[7];
    const float* bv = (const float*)d_in[8];
    const float* Wo = (const float*)d_in[9];
    const float* bo = (const float*)d_in[10];
    float* out = (float*)d_out;

    cudaFuncSetAttribute(attn_bf16, cudaFuncAttributeMaxDynamicSharedMemorySize, ATTN_SMEM_BYTES);
    cudaFuncSetAttribute(gemm_cp,   cudaFuncAttributeMaxDynamicSharedMemorySize, GEMM_SMEM);

    void *p_ebf, *p_wq, *p_wkv, *p_wo, *p_hn, *p_q, *p_k, *p_v, *p_ao;
    cudaGetSymbolAddress(&p_ebf, g_ebf);
    cudaGetSymbolAddress(&p_wq,  g_wqb);
    cudaGetSymbolAddress(&p_wkv, g_wkv);
    cudaGetSymbolAddress(&p_wo,  g_wob);
    cudaGetSymbolAddress(&p_hn,  g_hnb);
    cudaGetSymbolAddress(&p_q,   g_qb);
    cudaGetSymbolAddress(&p_k,   g_kb);
    cudaGetSymbolAddress(&p_v,   g_vb);
    cudaGetSymbolAddress(&p_ao,  g_aob);

    // node 1: residual out = h
    cudaMemcpyAsync(out, h, (size_t)4 * 1024 * 1024 * sizeof(float),
                    cudaMemcpyDeviceToDevice, 0);

    // nodes 2-4
    f2bf<<<16384, 256>>>((const float4*)e, (bf162*)p_ebf, 4194304);
    f2bf_cat<<<1024, 256>>>((const float4*)Wk, (const float4*)Wv, (bf162*)p_wkv);
    rmsnorm_bf16<<<4096, 256>>>(h, g, (bf16*)p_hn);

    // node 5 (profiled): fused K+V projection [16384,1024]@[1024,2048]
    gemm_cp<<<dim3(8, 128), 512, GEMM_SMEM>>>((const bf16*)p_ebf, (const bf16*)p_wkv,
                                              bk, bv, (bf16*)p_k, (bf16*)p_v,
                                              nullptr, 2048, 0);

    f2bf<<<1024, 256>>>((const float4*)Wq, (bf162*)p_wq, 262144);
    f2bf<<<1024, 256>>>((const float4*)Wo, (bf162*)p_wo, 262144);
    gemm_cp<<<dim3(4, 32), 512, GEMM_SMEM>>>((const bf16*)p_hn, (const bf16*)p_wq,
                                             bq, bq, (bf16*)p_q, (bf16*)p_q,
                                             nullptr, 1024, 0);

    attn_bf16<<<1024, 256, ATTN_SMEM_BYTES>>>((const bf16*)p_q, (const bf16*)p_k,
                                              (const bf16*)p_v, (bf16*)p_ao);

    gemm_cp<<<dim3(4, 32), 512, GEMM_SMEM>>>((const bf16*)p_ao, (const bf16*)p_wo,
                                             bo, bo, nullptr, nullptr,
                                             out, 1024, 1);
}